// round 8
// baseline (speedup 1.0000x reference)
#include <cuda_runtime.h>
#include <cstdint>

// ---------------- problem constants ----------------
#define BB    8
#define CN    128
#define HN    128
#define WN    128
#define HWN   16384
#define CHWN  (CN*HWN)                 // 2,097,152
#define BCHWN (BB*CHWN)                // 16,777,216
#define NPIX  (BB*HWN)                 // 131,072
#define NSPLIT 16

#define PITCH 133                      // smem row pitch in 4B words
#define TSZ   (128*PITCH)              // 17024 words per tile
#define SMEM_BYTES ((2*TSZ + 256) * 4) // 137216 B

// ---------------- device scratch ----------------
__device__ float g_pre [6ull*BCHWN];
__device__ float g_post[6ull*BCHWN];
__device__ float g_mean[2*NPIX];
__device__ float g_rstd[2*NPIX];
__device__ float g_Spart[2ull*NSPLIT*BB*CN*CN];
__device__ float g_S   [2ull*BB*CN*CN];
__device__ float g_A   [2ull*BCHWN];
__device__ float g_lin [1ull*BCHWN];

// ---------------- mma.sync tf32 helpers (3xTF32 compensated) ----------------
__device__ __forceinline__ void split2(float x, uint32_t& hi, uint32_t& lo) {
    uint32_t h;
    asm("cvt.rna.tf32.f32 %0, %1;" : "=r"(h) : "f"(x));
    float l = x - __uint_as_float(h);
    uint32_t lw_;
    asm("cvt.rna.tf32.f32 %0, %1;" : "=r"(lw_) : "f"(l));
    hi = h; lo = lw_;
}
__device__ __forceinline__ void mma8(float c[4], const uint32_t a[4],
                                     uint32_t b0, uint32_t b1) {
    asm volatile(
        "mma.sync.aligned.m16n8k8.row.col.f32.tf32.tf32.f32 "
        "{%0,%1,%2,%3},{%4,%5,%6,%7},{%8,%9},{%0,%1,%2,%3};"
        : "+f"(c[0]), "+f"(c[1]), "+f"(c[2]), "+f"(c[3])
        : "r"(a[0]), "r"(a[1]), "r"(a[2]), "r"(a[3]), "r"(b0), "r"(b1));
}

// C[128x128] += A[128x128] * B^T, A smem [m][k] f32, B smem [n][k] f32.
// 8 warps: warp tile 32(m) x 64(n); 3xTF32 split per product.
__device__ __forceinline__ void gemm128(const float* __restrict__ As,
                                        const float* __restrict__ Bs,
                                        float c4[2][8][4],
                                        int m0, int n0w, int r, int q) {
#pragma unroll 2
    for (int ks = 0; ks < 16; ks++) {
        int k0 = ks * 8;
        uint32_t ahi[2][4], alo[2][4];
#pragma unroll
        for (int mi = 0; mi < 2; mi++) {
            const float* ap = As + (m0 + mi * 16 + r) * PITCH + k0 + q;
            float av0 = ap[0], av1 = ap[8 * PITCH], av2 = ap[4], av3 = ap[8 * PITCH + 4];
            split2(av0, ahi[mi][0], alo[mi][0]);
            split2(av1, ahi[mi][1], alo[mi][1]);
            split2(av2, ahi[mi][2], alo[mi][2]);
            split2(av3, ahi[mi][3], alo[mi][3]);
        }
#pragma unroll
        for (int ni = 0; ni < 8; ni++) {
            const float* bp = Bs + (n0w + ni * 8 + r) * PITCH + k0 + q;
            uint32_t b0h, b0l, b1h, b1l;
            split2(bp[0], b0h, b0l);
            split2(bp[4], b1h, b1l);
#pragma unroll
            for (int mi = 0; mi < 2; mi++) {
                mma8(c4[mi][ni], ahi[mi], b0h, b1h);
                mma8(c4[mi][ni], alo[mi], b0h, b1h);
                mma8(c4[mi][ni], ahi[mi], b0l, b1l);
            }
        }
    }
}
#define ZERO_C(c4) {                                   \
    _Pragma("unroll") for (int mi = 0; mi < 2; mi++)   \
    _Pragma("unroll") for (int ni = 0; ni < 8; ni++)   \
    _Pragma("unroll") for (int t = 0; t < 4; t++) (c4)[mi][ni][t] = 0.f; }

// ---------------- kernel 0: LayerNorm stats per pixel ----------------
__global__ __launch_bounds__(256) void k_stats(const float* __restrict__ Fi,
                                               const float* __restrict__ Fw) {
    int inp = blockIdx.y;
    const float* X = inp ? Fw : Fi;
    int p = blockIdx.x * 256 + threadIdx.x;
    int b = p >> 14, pix = p & (HWN - 1);
    const float* Xb = X + (size_t)b * CHWN + pix;
    float s = 0.f, ss = 0.f;
#pragma unroll 8
    for (int c = 0; c < CN; c++) {
        float v = Xb[(size_t)c * HWN];
        s += v; ss += v * v;
    }
    float m = s * (1.f / CN);
    float var = ss * (1.f / CN) - m * m;
    g_mean[inp * NPIX + p] = m;
    g_rstd[inp * NPIX + p] = rsqrtf(var + 1e-5f);
}

// ---------------- kernel 1: fused LN + 3x(1x1 conv) ----------------
// C[o][pix] = W[o][c] * Xn[pix][c]^T
__global__ __launch_bounds__(256) void k_ln_c11(
    const float* __restrict__ Fi, const float* __restrict__ Fw,
    const float* __restrict__ g1, const float* __restrict__ g2,
    const float* wq, const float* wk, const float* wv,
    const float* bq, const float* bk, const float* bv,
    const float* wq2, const float* wk2, const float* wv2,
    const float* bq2, const float* bk2, const float* bv2) {
    extern __shared__ float sm[];
    float* As = sm;                    // W  [o][c]
    float* Bs = sm + TSZ;              // Xn [pix][c]
    float* mu_s = sm + 2 * TSZ;
    float* rs_s = mu_s + 128;

    int tid = threadIdx.x, wid = tid >> 5, lane = tid & 31;
    int inp = blockIdx.y;
    int p0 = blockIdx.x * 128;
    int b = p0 >> 14, pix0 = p0 & (HWN - 1);
    const float* X = inp ? Fw : Fi;
    const float* gamma = inp ? g2 : g1;
    const float* Ws3[3] = { inp ? wq2 : wq, inp ? wk2 : wk, inp ? wv2 : wv };
    const float* Bs3[3] = { inp ? bq2 : bq, inp ? bk2 : bk, inp ? bv2 : bv };

    if (tid < 128) {
        mu_s[tid] = g_mean[inp * NPIX + p0 + tid];
        rs_s[tid] = g_rstd[inp * NPIX + p0 + tid];
    }
    __syncthreads();

    const float* Xb = X + (size_t)b * CHWN + pix0;
#pragma unroll 4
    for (int it = 0; it < 64; it++) {
        int idx = it * 256 + tid;
        int c = idx >> 7, p = idx & 127;
        float v = Xb[(size_t)c * HWN + p];
        Bs[p * PITCH + c] = (v - mu_s[p]) * rs_s[p] * __ldg(&gamma[c]);
    }

    int m0 = (wid & 3) * 32, n0w = (wid >> 2) * 64;
    int r = lane >> 2, q = lane & 3;

    for (int i = 0; i < 3; i++) {
        if (i) __syncthreads();
        const float* Wm = Ws3[i];
#pragma unroll 4
        for (int it = 0; it < 64; it++) {
            int idx = it * 256 + tid;
            As[(idx >> 7) * PITCH + (idx & 127)] = Wm[idx];
        }
        __syncthreads();
        float c4[2][8][4];
        ZERO_C(c4);
        gemm128(As, Bs, c4, m0, n0w, r, q);

        const float* bias = Bs3[i];
        float* Ob = g_pre + ((size_t)(inp * 3 + i) * BB + b) * CHWN;
#pragma unroll
        for (int mi = 0; mi < 2; mi++) {
            int o0 = m0 + mi * 16 + r;
            float bo0 = __ldg(&bias[o0]), bo1 = __ldg(&bias[o0 + 8]);
#pragma unroll
            for (int ni = 0; ni < 8; ni++) {
                int col = pix0 + n0w + ni * 8 + 2 * q;
                Ob[(size_t)o0 * HWN + col]           = c4[mi][ni][0] + bo0;
                Ob[(size_t)o0 * HWN + col + 1]       = c4[mi][ni][1] + bo0;
                Ob[(size_t)(o0 + 8) * HWN + col]     = c4[mi][ni][2] + bo1;
                Ob[(size_t)(o0 + 8) * HWN + col + 1] = c4[mi][ni][3] + bo1;
            }
        }
    }
}

// ---------------- kernel 2: depthwise 3x3, SAME ----------------
__global__ __launch_bounds__(256) void k_dw(
    const float* d0, const float* d1, const float* d2,
    const float* d3, const float* d4, const float* d5,
    const float* e0, const float* e1, const float* e2,
    const float* e3, const float* e4, const float* e5) {
    int br = blockIdx.z, b = blockIdx.y;
    int e = blockIdx.x * 256 + threadIdx.x;
    int c = e >> 14, pix = e & (HWN - 1);
    int h = pix >> 7, w = pix & 127;
    const float* Wd6[6] = {d0, d1, d2, d3, d4, d5};
    const float* Bd6[6] = {e0, e1, e2, e3, e4, e5};
    const float* Wd = Wd6[br] + c * 9;
    const float* In = g_pre + (size_t)br * BCHWN + (size_t)b * CHWN + (size_t)c * HWN;
    float acc = __ldg(&Bd6[br][c]);
#pragma unroll
    for (int dy = -1; dy <= 1; dy++) {
        int hh = h + dy;
        if ((unsigned)hh < (unsigned)HN) {
            const float* row = In + hh * WN;
#pragma unroll
            for (int dx = -1; dx <= 1; dx++) {
                int ww = w + dx;
                if ((unsigned)ww < (unsigned)WN)
                    acc += __ldg(&Wd[(dy + 1) * 3 + (dx + 1)]) * row[ww];
            }
        }
    }
    g_post[(size_t)br * BCHWN + (size_t)b * CHWN + e] = acc;
}

// ---------------- kernel 3: S partials via mma ----------------
// C[c][d] = sum_n Q[n][c] K[n][d]
__global__ __launch_bounds__(256) void k_qk() {
    extern __shared__ float sm[];
    float* As = sm;
    float* Bs = sm + TSZ;
    int tid = threadIdx.x, wid = tid >> 5, lane = tid & 31;
    int s = blockIdx.x, b = blockIdx.y, att = blockIdx.z;
    const float* Q = g_post + (size_t)(att == 0 ? 0 : 3) * BCHWN + (size_t)b * CHWN;
    const float* K = g_post + (size_t)(att == 0 ? 4 : 1) * BCHWN + (size_t)b * CHWN;

    int m0 = (wid & 3) * 32, n0w = (wid >> 2) * 64;
    int r = lane >> 2, q = lane & 3;
    float c4[2][8][4];
    ZERO_C(c4);

    for (int kc = 0; kc < 8; kc++) {
        if (kc) __syncthreads();
        size_t nbase = (size_t)(s * 1024 + kc * 128) * CN;
#pragma unroll 4
        for (int it = 0; it < 64; it++) {
            int idx = it * 256 + tid;
            int nn = idx >> 7, cc = idx & 127;
            As[cc * PITCH + nn] = Q[nbase + (size_t)nn * CN + cc];
            Bs[cc * PITCH + nn] = K[nbase + (size_t)nn * CN + cc];
        }
        __syncthreads();
        gemm128(As, Bs, c4, m0, n0w, r, q);
    }

    float* Sp = g_Spart + ((size_t)(att * NSPLIT + s) * BB + b) * (CN * CN);
#pragma unroll
    for (int mi = 0; mi < 2; mi++) {
        int c0 = m0 + mi * 16 + r;
#pragma unroll
        for (int ni = 0; ni < 8; ni++) {
            int col = n0w + ni * 8 + 2 * q;
            Sp[c0 * CN + col]           = c4[mi][ni][0];
            Sp[c0 * CN + col + 1]       = c4[mi][ni][1];
            Sp[(c0 + 8) * CN + col]     = c4[mi][ni][2];
            Sp[(c0 + 8) * CN + col + 1] = c4[mi][ni][3];
        }
    }
}

// ---------------- kernel 4: reduce partials + softmax ----------------
__global__ __launch_bounds__(256) void k_softmax() {
    int row  = blockIdx.x * 8 + (threadIdx.x >> 5);
    int lane = threadIdx.x & 31;
    int att = row >> 10, rb = row & 1023, b = rb >> 7, c = rb & 127;
    float v[4];
#pragma unroll
    for (int q = 0; q < 4; q++) {
        int d = lane + 32 * q;
        float s = 0.f;
        for (int sp = 0; sp < NSPLIT; sp++)
            s += g_Spart[((size_t)(att * NSPLIT + sp) * BB + b) * (CN * CN) + c * CN + d];
        v[q] = s;
    }
    float mx = fmaxf(fmaxf(v[0], v[1]), fmaxf(v[2], v[3]));
#pragma unroll
    for (int o = 16; o > 0; o >>= 1) mx = fmaxf(mx, __shfl_xor_sync(0xffffffffu, mx, o));
    float e[4], sum = 0.f;
#pragma unroll
    for (int q = 0; q < 4; q++) { e[q] = __expf(v[q] - mx); sum += e[q]; }
#pragma unroll
    for (int o = 16; o > 0; o >>= 1) sum += __shfl_xor_sync(0xffffffffu, sum, o);
    float inv = 1.f / sum;
#pragma unroll
    for (int q = 0; q < 4; q++)
        g_S[(size_t)(att * BB + b) * (CN * CN) + c * CN + lane + 32 * q] = e[q] * inv;
}

// ---------------- kernel 5: A@V via mma ----------------
// C[c][n] = sum_d S[c][d] V[d][n]
__global__ __launch_bounds__(256) void k_av() {
    extern __shared__ float sm[];
    float* As = sm;
    float* Bs = sm + TSZ;
    int tid = threadIdx.x, wid = tid >> 5, lane = tid & 31;
    int nt = blockIdx.x, b = blockIdx.y, att = blockIdx.z;
    const float* S = g_S + (size_t)(att * BB + b) * (CN * CN);
    const float* V = g_post + (size_t)(att == 0 ? 5 : 2) * BCHWN + (size_t)b * CHWN;
    int n0 = nt * 128;

#pragma unroll 4
    for (int it = 0; it < 64; it++) {
        int idx = it * 256 + tid;
        As[(idx >> 7) * PITCH + (idx & 127)] = S[idx];
    }
#pragma unroll 4
    for (int it = 0; it < 64; it++) {
        int idx = it * 256 + tid;
        int dd = idx >> 7, p = idx & 127;
        Bs[p * PITCH + dd] = V[(size_t)dd * HWN + n0 + p];
    }
    __syncthreads();

    int m0 = (wid & 3) * 32, n0w = (wid >> 2) * 64;
    int r = lane >> 2, q = lane & 3;
    float c4[2][8][4];
    ZERO_C(c4);
    gemm128(As, Bs, c4, m0, n0w, r, q);

    float* Out = g_A + (size_t)att * BCHWN + (size_t)b * CHWN;
#pragma unroll
    for (int mi = 0; mi < 2; mi++) {
        int c0 = m0 + mi * 16 + r;
#pragma unroll
        for (int ni = 0; ni < 8; ni++) {
            int col = n0 + n0w + ni * 8 + 2 * q;
            Out[(size_t)c0 * HWN + col]           = c4[mi][ni][0];
            Out[(size_t)c0 * HWN + col + 1]       = c4[mi][ni][1];
            Out[(size_t)(c0 + 8) * HWN + col]     = c4[mi][ni][2];
            Out[(size_t)(c0 + 8) * HWN + col + 1] = c4[mi][ni][3];
        }
    }
}

// ---------------- kernel 6: final linear via mma ----------------
// C[pix][co] = sum_t flat[pix][t] lw[co][t]
__global__ __launch_bounds__(256) void k_final(const float* __restrict__ lw,
                                               const float* __restrict__ lb) {
    extern __shared__ float sm[];
    float* As = sm;                    // flat [pix][t]
    float* Bs = sm + TSZ;              // lw   [co][t]
    int tid = threadIdx.x, wid = tid >> 5, lane = tid & 31;
    int nt = blockIdx.x, b = blockIdx.y;
    int n0 = nt * 128;

    int m0 = (wid & 3) * 32, n0w = (wid >> 2) * 64;
    int r = lane >> 2, q = lane & 3;
    float c4[2][8][4];
    ZERO_C(c4);

    for (int part = 0; part < 2; part++) {
        if (part) __syncthreads();
        const float* Abuf = g_A + (size_t)(part * BB + b) * CHWN + (size_t)n0 * CN;
#pragma unroll 4
        for (int it = 0; it < 64; it++) {
            int idx = it * 256 + tid;
            As[(idx >> 7) * PITCH + (idx & 127)] = Abuf[idx];
        }
#pragma unroll 4
        for (int it = 0; it < 64; it++) {
            int idx = it * 256 + tid;
            int co = idx >> 7, t = idx & 127;
            Bs[co * PITCH + t] = lw[co * 256 + part * 128 + t];
        }
        __syncthreads();
        gemm128(As, Bs, c4, m0, n0w, r, q);
    }

    float* Ob = g_lin + (size_t)b * CHWN;
#pragma unroll
    for (int mi = 0; mi < 2; mi++) {
        int p0r = n0 + m0 + mi * 16 + r;
#pragma unroll
        for (int ni = 0; ni < 8; ni++) {
            int col = n0w + ni * 8 + 2 * q;
            float b0 = __ldg(&lb[col]), b1 = __ldg(&lb[col + 1]);
            Ob[(size_t)p0r * CN + col]           = c4[mi][ni][0] + b0;
            Ob[(size_t)p0r * CN + col + 1]       = c4[mi][ni][1] + b1;
            Ob[(size_t)(p0r + 8) * CN + col]     = c4[mi][ni][2] + b0;
            Ob[(size_t)(p0r + 8) * CN + col + 1] = c4[mi][ni][3] + b1;
        }
    }
}

// ---------------- kernel 7: tail transpose + residual ----------------
__global__ __launch_bounds__(256) void k_tail(const float* __restrict__ Fi,
                                              const float* __restrict__ Fw,
                                              float* __restrict__ out) {
    __shared__ float tile[32][33];
    int b  = blockIdx.z;
    int r0 = blockIdx.x * 32;
    int c0 = blockIdx.y * 32;
    const float* In = g_lin + (size_t)b * CHWN;
    int tx = threadIdx.x & 31, ty = threadIdx.x >> 5;
#pragma unroll
    for (int s2 = 0; s2 < 4; s2++) {
        int cc = c0 + ty + 8 * s2;
        tile[ty + 8 * s2][tx] = In[(size_t)cc * HWN + r0 + tx];
    }
    __syncthreads();
    size_t base = (size_t)b * CHWN;
#pragma unroll
    for (int s2 = 0; s2 < 4; s2++) {
        int r = r0 + ty + 8 * s2;
        size_t idx = base + (size_t)r * CN + c0 + tx;
        out[idx] = tile[tx][ty + 8 * s2] + Fi[idx] + Fw[idx];
    }
}

// ---------------- launch ----------------
extern "C" void kernel_launch(void* const* d_in, const int* in_sizes, int n_in,
                              void* d_out, int out_size) {
    const float* Fi = (const float*)d_in[0];
    const float* Fw = (const float*)d_in[1];
    const float* g1 = (const float*)d_in[2];
    const float* g2 = (const float*)d_in[3];

    const float *qw1, *kw1, *vw1, *qw2, *kw2, *vw2;
    const float *qb1, *kb1, *vb1, *qb2, *kb2, *vb2;
    const float *qdw1, *kdw1, *vdw1, *qdw2, *kdw2, *vdw2;
    const float *qdb1, *kdb1, *vdb1, *qdb2, *kdb2, *vdb2;
    const float *lw, *lb;

    if (in_sizes[5] == CN) {
        qw1 = (const float*)d_in[4];  qb1 = (const float*)d_in[5];
        kw1 = (const float*)d_in[6];  kb1 = (const float*)d_in[7];
        vw1 = (const float*)d_in[8];  vb1 = (const float*)d_in[9];
        qw2 = (const float*)d_in[10]; qb2 = (const float*)d_in[11];
        kw2 = (const float*)d_in[12]; kb2 = (const float*)d_in[13];
        vw2 = (const float*)d_in[14]; vb2 = (const float*)d_in[15];
        qdw1 = (const float*)d_in[16]; qdb1 = (const float*)d_in[17];
        kdw1 = (const float*)d_in[18]; kdb1 = (const float*)d_in[19];
        vdw1 = (const float*)d_in[20]; vdb1 = (const float*)d_in[21];
        qdw2 = (const float*)d_in[22]; qdb2 = (const float*)d_in[23];
        kdw2 = (const float*)d_in[24]; kdb2 = (const float*)d_in[25];
        vdw2 = (const float*)d_in[26]; vdb2 = (const float*)d_in[27];
    } else {
        qw1 = (const float*)d_in[4];  kw1 = (const float*)d_in[5];
        vw1 = (const float*)d_in[6];  qw2 = (const float*)d_in[7];
        kw2 = (const float*)d_in[8];  vw2 = (const float*)d_in[9];
        qb1 = (const float*)d_in[10]; kb1 = (const float*)d_in[11];
        vb1 = (const float*)d_in[12]; qb2 = (const float*)d_in[13];
        kb2 = (const float*)d_in[14]; vb2 = (const float*)d_in[15];
        qdw1 = (const float*)d_in[16]; kdw1 = (const float*)d_in[17];
        vdw1 = (const float*)d_in[18]; qdw2 = (const float*)d_in[19];
        kdw2 = (const float*)d_in[20]; vdw2 = (const float*)d_in[21];
        qdb1 = (const float*)d_in[22]; kdb1 = (const float*)d_in[23];
        vdb1 = (const float*)d_in[24]; qdb2 = (const float*)d_in[25];
        kdb2 = (const float*)d_in[26]; vdb2 = (const float*)d_in[27];
    }
    lw = (const float*)d_in[28];
    lb = (const float*)d_in[29];
    float* out = (float*)d_out;

    cudaFuncSetAttribute(k_ln_c11, cudaFuncAttributeMaxDynamicSharedMemorySize, SMEM_BYTES);
    cudaFuncSetAttribute(k_qk,     cudaFuncAttributeMaxDynamicSharedMemorySize, SMEM_BYTES);
    cudaFuncSetAttribute(k_av,     cudaFuncAttributeMaxDynamicSharedMemorySize, SMEM_BYTES);
    cudaFuncSetAttribute(k_final,  cudaFuncAttributeMaxDynamicSharedMemorySize, SMEM_BYTES);

    k_stats  <<<dim3(NPIX / 256, 2), 256>>>(Fi, Fw);
    k_ln_c11 <<<dim3(NPIX / 128, 2), 256, SMEM_BYTES>>>(Fi, Fw, g1, g2,
                                                        qw1, kw1, vw1, qb1, kb1, vb1,
                                                        qw2, kw2, vw2, qb2, kb2, vb2);
    k_dw     <<<dim3(CHWN / 256, BB, 6), 256>>>(qdw1, kdw1, vdw1, qdw2, kdw2, vdw2,
                                                qdb1, kdb1, vdb1, qdb2, kdb2, vdb2);
    k_qk     <<<dim3(NSPLIT, BB, 2), 256, SMEM_BYTES>>>();
    k_softmax<<<dim3(256), 256>>>();
    k_av     <<<dim3(HWN / 128, BB, 2), 256, SMEM_BYTES>>>();
    k_final  <<<dim3(HWN / 128, BB), 256, SMEM_BYTES>>>(lw, lb);
    k_tail   <<<dim3(HWN / 32, CN / 32, BB), 256>>>(Fi, Fw, out);
}

// round 9
// speedup vs baseline: 1.1441x; 1.1441x over previous
#include <cuda_runtime.h>
#include <cstdint>

// ---------------- problem constants ----------------
#define BB    8
#define CN    128
#define HN    128
#define WN    128
#define HWN   16384
#define CHWN  (CN*HWN)                 // 2,097,152
#define BCHWN (BB*CHWN)                // 16,777,216
#define NPIX  (BB*HWN)                 // 131,072
#define NSPLIT 16

// smem tile layouts (uint2 {tf32_hi, tf32_lo} elements):
//  KM layout: [k][m], 64 k-rows x 128 m-cols, pitch PKM uint2
//  MK layout: [m][k], 128 m-rows x 64 k-cols, pitch PMK uint2
#define PKM 130
#define PMK 66
#define TILE_BYTES 67584               // max(128*66, 64*130)*8 = 67584
#define SMEM_BYTES (2*TILE_BYTES + 1024)

// ---------------- device scratch ----------------
__device__ float g_pre [6ull*BCHWN];
__device__ float g_post[6ull*BCHWN];
__device__ float g_mean[2*NPIX];
__device__ float g_rstd[2*NPIX];
__device__ float g_Spart[2ull*NSPLIT*BB*CN*CN];
__device__ float g_S   [2ull*BB*CN*CN];
__device__ float g_A   [2ull*BCHWN];
__device__ float g_lin [1ull*BCHWN];

// ---------------- tf32 split + mma ----------------
__device__ __forceinline__ uint2 split2(float x) {
    uint32_t h;
    asm("cvt.rna.tf32.f32 %0, %1;" : "=r"(h) : "f"(x));
    float l = x - __uint_as_float(h);
    uint32_t lo;
    asm("cvt.rna.tf32.f32 %0, %1;" : "=r"(lo) : "f"(l));
    return make_uint2(h, lo);
}
__device__ __forceinline__ void mma8(float c[4], const uint32_t a[4],
                                     uint32_t b0, uint32_t b1) {
    asm volatile(
        "mma.sync.aligned.m16n8k8.row.col.f32.tf32.tf32.f32 "
        "{%0,%1,%2,%3},{%4,%5,%6,%7},{%8,%9},{%0,%1,%2,%3};"
        : "+f"(c[0]), "+f"(c[1]), "+f"(c[2]), "+f"(c[3])
        : "r"(a[0]), "r"(a[1]), "r"(a[2]), "r"(a[3]), "r"(b0), "r"(b1));
}

// C[128x128] += A * B^T over a 64-wide K chunk; warp tile 32(m) x 32(n).
// AKM/BKM: operand tile layout (true = [k][m], false = [m][k]).
template<bool AKM, bool BKM>
__device__ __forceinline__ void gemm64(const uint2* __restrict__ A2,
                                       const uint2* __restrict__ B2,
                                       float c4[2][4][4],
                                       int m0, int n0w, int r, int q) {
#pragma unroll
    for (int ks = 0; ks < 8; ks++) {
        int k0 = ks * 8;
        uint32_t ahi[2][4], alo[2][4];
#pragma unroll
        for (int mi = 0; mi < 2; mi++) {
            int m = m0 + mi * 16 + r;
            uint2 p0, p1, p2, p3;
            if (AKM) {
                p0 = A2[(k0 + q) * PKM + m];
                p1 = A2[(k0 + q) * PKM + m + 8];
                p2 = A2[(k0 + q + 4) * PKM + m];
                p3 = A2[(k0 + q + 4) * PKM + m + 8];
            } else {
                p0 = A2[m * PMK + k0 + q];
                p1 = A2[(m + 8) * PMK + k0 + q];
                p2 = A2[m * PMK + k0 + q + 4];
                p3 = A2[(m + 8) * PMK + k0 + q + 4];
            }
            ahi[mi][0] = p0.x; ahi[mi][1] = p1.x; ahi[mi][2] = p2.x; ahi[mi][3] = p3.x;
            alo[mi][0] = p0.y; alo[mi][1] = p1.y; alo[mi][2] = p2.y; alo[mi][3] = p3.y;
        }
#pragma unroll
        for (int ni = 0; ni < 4; ni++) {
            int col = n0w + ni * 8 + r;
            uint2 pb0, pb1;
            if (BKM) {
                pb0 = B2[(k0 + q) * PKM + col];
                pb1 = B2[(k0 + q + 4) * PKM + col];
            } else {
                pb0 = B2[col * PMK + k0 + q];
                pb1 = B2[col * PMK + k0 + q + 4];
            }
#pragma unroll
            for (int mi = 0; mi < 2; mi++) {
                mma8(c4[mi][ni], ahi[mi], pb0.x, pb1.x);
                mma8(c4[mi][ni], alo[mi], pb0.x, pb1.x);
                mma8(c4[mi][ni], ahi[mi], pb0.y, pb1.y);
            }
        }
    }
}
#define ZERO_C(c4) {                                   \
    _Pragma("unroll") for (int mi = 0; mi < 2; mi++)   \
    _Pragma("unroll") for (int ni = 0; ni < 4; ni++)   \
    _Pragma("unroll") for (int t = 0; t < 4; t++) (c4)[mi][ni][t] = 0.f; }

// ---------------- kernel 0: LayerNorm stats per pixel ----------------
__global__ __launch_bounds__(256) void k_stats(const float* __restrict__ Fi,
                                               const float* __restrict__ Fw) {
    int inp = blockIdx.y;
    const float* X = inp ? Fw : Fi;
    int p = blockIdx.x * 256 + threadIdx.x;
    int b = p >> 14, pix = p & (HWN - 1);
    const float* Xb = X + (size_t)b * CHWN + pix;
    float s = 0.f, ss = 0.f;
#pragma unroll 8
    for (int c = 0; c < CN; c++) {
        float v = Xb[(size_t)c * HWN];
        s += v; ss += v * v;
    }
    float m = s * (1.f / CN);
    float var = ss * (1.f / CN) - m * m;
    g_mean[inp * NPIX + p] = m;
    g_rstd[inp * NPIX + p] = rsqrtf(var + 1e-5f);
}

// ---------------- kernel 1: fused LN + 3x(1x1 conv) ----------------
// C[o][pix] = sum_c W[o][c] * Xn[pix][c];  A=W (MK), B=Xn (KM)
__global__ __launch_bounds__(512, 1) void k_ln_c11(
    const float* __restrict__ Fi, const float* __restrict__ Fw,
    const float* __restrict__ g1, const float* __restrict__ g2,
    const float* wq, const float* wk, const float* wv,
    const float* bq, const float* bk, const float* bv,
    const float* wq2, const float* wk2, const float* wv2,
    const float* bq2, const float* bk2, const float* bv2) {
    extern __shared__ char smraw[];
    uint2* A2 = (uint2*)smraw;
    uint2* B2 = (uint2*)(smraw + TILE_BYTES);
    float* mu_s = (float*)(smraw + 2 * TILE_BYTES);
    float* rs_s = mu_s + 128;

    int tid = threadIdx.x, wid = tid >> 5, lane = tid & 31;
    int inp = blockIdx.y;
    int p0 = blockIdx.x * 128;
    int b = p0 >> 14, pix0 = p0 & (HWN - 1);
    const float* X = inp ? Fw : Fi;
    const float* gamma = inp ? g2 : g1;
    const float* Ws3[3] = { inp ? wq2 : wq, inp ? wk2 : wk, inp ? wv2 : wv };
    const float* Bs3[3] = { inp ? bq2 : bq, inp ? bk2 : bk, inp ? bv2 : bv };

    if (tid < 128) {
        mu_s[tid] = g_mean[inp * NPIX + p0 + tid];
        rs_s[tid] = g_rstd[inp * NPIX + p0 + tid];
    }
    __syncthreads();

    int m0 = (wid & 3) * 32, n0w = (wid >> 2) * 32;
    int r = lane >> 2, q = lane & 3;
    const float* Xb = X + (size_t)b * CHWN + pix0;

    for (int i = 0; i < 3; i++) {
        const float* Wm = Ws3[i];
        float c4[2][4][4];
        ZERO_C(c4);
        for (int ch = 0; ch < 2; ch++) {
            int c0 = ch * 64;
            __syncthreads();
#pragma unroll
            for (int it = 0; it < 16; it++) {        // B = Xn chunk (KM)
                int idx = it * 512 + tid;
                int kc = idx >> 7, p = idx & 127;
                float v = Xb[(size_t)(c0 + kc) * HWN + p];
                B2[kc * PKM + p] = split2((v - mu_s[p]) * rs_s[p] * __ldg(&gamma[c0 + kc]));
            }
#pragma unroll
            for (int it = 0; it < 16; it++) {        // A = W chunk (MK)
                int idx = it * 512 + tid;
                int o = idx >> 6, kc = idx & 63;
                A2[o * PMK + kc] = split2(Wm[o * CN + c0 + kc]);
            }
            __syncthreads();
            gemm64<false, true>(A2, B2, c4, m0, n0w, r, q);
        }
        const float* bias = Bs3[i];
        float* Ob = g_pre + ((size_t)(inp * 3 + i) * BB + b) * CHWN;
#pragma unroll
        for (int mi = 0; mi < 2; mi++) {
            int o0 = m0 + mi * 16 + r;
            float bo0 = __ldg(&bias[o0]), bo1 = __ldg(&bias[o0 + 8]);
#pragma unroll
            for (int ni = 0; ni < 4; ni++) {
                int col = pix0 + n0w + ni * 8 + 2 * q;
                Ob[(size_t)o0 * HWN + col]           = c4[mi][ni][0] + bo0;
                Ob[(size_t)o0 * HWN + col + 1]       = c4[mi][ni][1] + bo0;
                Ob[(size_t)(o0 + 8) * HWN + col]     = c4[mi][ni][2] + bo1;
                Ob[(size_t)(o0 + 8) * HWN + col + 1] = c4[mi][ni][3] + bo1;
            }
        }
    }
}

// ---------------- kernel 2: depthwise 3x3, SAME ----------------
__global__ __launch_bounds__(256) void k_dw(
    const float* d0, const float* d1, const float* d2,
    const float* d3, const float* d4, const float* d5,
    const float* e0, const float* e1, const float* e2,
    const float* e3, const float* e4, const float* e5) {
    int br = blockIdx.z, b = blockIdx.y;
    int e = blockIdx.x * 256 + threadIdx.x;
    int c = e >> 14, pix = e & (HWN - 1);
    int h = pix >> 7, w = pix & 127;
    const float* Wd6[6] = {d0, d1, d2, d3, d4, d5};
    const float* Bd6[6] = {e0, e1, e2, e3, e4, e5};
    const float* Wd = Wd6[br] + c * 9;
    const float* In = g_pre + (size_t)br * BCHWN + (size_t)b * CHWN + (size_t)c * HWN;
    float acc = __ldg(&Bd6[br][c]);
#pragma unroll
    for (int dy = -1; dy <= 1; dy++) {
        int hh = h + dy;
        if ((unsigned)hh < (unsigned)HN) {
            const float* row = In + hh * WN;
#pragma unroll
            for (int dx = -1; dx <= 1; dx++) {
                int ww = w + dx;
                if ((unsigned)ww < (unsigned)WN)
                    acc += __ldg(&Wd[(dy + 1) * 3 + (dx + 1)]) * row[ww];
            }
        }
    }
    g_post[(size_t)br * BCHWN + (size_t)b * CHWN + e] = acc;
}

// ---------------- kernel 3: S partials ----------------
// C[c][d] = sum_n Q[n][c] K[n][d];  A=Q (KM), B=K (KM)
__global__ __launch_bounds__(512, 1) void k_qk() {
    extern __shared__ char smraw[];
    uint2* A2 = (uint2*)smraw;
    uint2* B2 = (uint2*)(smraw + TILE_BYTES);
    int tid = threadIdx.x, wid = tid >> 5, lane = tid & 31;
    int s = blockIdx.x, b = blockIdx.y, att = blockIdx.z;
    const float* Q = g_post + (size_t)(att == 0 ? 0 : 3) * BCHWN + (size_t)b * CHWN;
    const float* K = g_post + (size_t)(att == 0 ? 4 : 1) * BCHWN + (size_t)b * CHWN;

    int m0 = (wid & 3) * 32, n0w = (wid >> 2) * 32;
    int r = lane >> 2, q = lane & 3;
    float c4[2][4][4];
    ZERO_C(c4);

    for (int ch = 0; ch < 16; ch++) {
        size_t nbase = (size_t)(s * 1024 + ch * 64) * CN;
        __syncthreads();
#pragma unroll
        for (int it = 0; it < 16; it++) {
            int idx = it * 512 + tid;
            int nn = idx >> 7, cc = idx & 127;
            A2[nn * PKM + cc] = split2(Q[nbase + (size_t)nn * CN + cc]);
            B2[nn * PKM + cc] = split2(K[nbase + (size_t)nn * CN + cc]);
        }
        __syncthreads();
        gemm64<true, true>(A2, B2, c4, m0, n0w, r, q);
    }

    float* Sp = g_Spart + ((size_t)(att * NSPLIT + s) * BB + b) * (CN * CN);
#pragma unroll
    for (int mi = 0; mi < 2; mi++) {
        int c0 = m0 + mi * 16 + r;
#pragma unroll
        for (int ni = 0; ni < 4; ni++) {
            int col = n0w + ni * 8 + 2 * q;
            Sp[c0 * CN + col]           = c4[mi][ni][0];
            Sp[c0 * CN + col + 1]       = c4[mi][ni][1];
            Sp[(c0 + 8) * CN + col]     = c4[mi][ni][2];
            Sp[(c0 + 8) * CN + col + 1] = c4[mi][ni][3];
        }
    }
}

// ---------------- kernel 4: reduce partials + softmax ----------------
__global__ __launch_bounds__(256) void k_softmax() {
    int row  = blockIdx.x * 8 + (threadIdx.x >> 5);
    int lane = threadIdx.x & 31;
    int att = row >> 10, rb = row & 1023, b = rb >> 7, c = rb & 127;
    float v[4];
#pragma unroll
    for (int q = 0; q < 4; q++) {
        int d = lane + 32 * q;
        float s = 0.f;
        for (int sp = 0; sp < NSPLIT; sp++)
            s += g_Spart[((size_t)(att * NSPLIT + sp) * BB + b) * (CN * CN) + c * CN + d];
        v[q] = s;
    }
    float mx = fmaxf(fmaxf(v[0], v[1]), fmaxf(v[2], v[3]));
#pragma unroll
    for (int o = 16; o > 0; o >>= 1) mx = fmaxf(mx, __shfl_xor_sync(0xffffffffu, mx, o));
    float e[4], sum = 0.f;
#pragma unroll
    for (int q = 0; q < 4; q++) { e[q] = __expf(v[q] - mx); sum += e[q]; }
#pragma unroll
    for (int o = 16; o > 0; o >>= 1) sum += __shfl_xor_sync(0xffffffffu, sum, o);
    float inv = 1.f / sum;
#pragma unroll
    for (int q = 0; q < 4; q++)
        g_S[(size_t)(att * BB + b) * (CN * CN) + c * CN + lane + 32 * q] = e[q] * inv;
}

// ---------------- kernel 5: A@V ----------------
// C[npix][c] = sum_d V[d][n0+npix] * S[c][d];  A=V (KM), B=S (MK)
__global__ __launch_bounds__(512, 1) void k_av() {
    extern __shared__ char smraw[];
    uint2* A2 = (uint2*)smraw;
    uint2* B2 = (uint2*)(smraw + TILE_BYTES);
    int tid = threadIdx.x, wid = tid >> 5, lane = tid & 31;
    int nt = blockIdx.x, b = blockIdx.y, att = blockIdx.z;
    const float* S = g_S + (size_t)(att * BB + b) * (CN * CN);
    const float* V = g_post + (size_t)(att == 0 ? 5 : 2) * BCHWN + (size_t)b * CHWN;
    int n0 = nt * 128;

    int m0 = (wid & 3) * 32, n0w = (wid >> 2) * 32;
    int r = lane >> 2, q = lane & 3;
    float c4[2][4][4];
    ZERO_C(c4);

    for (int ch = 0; ch < 2; ch++) {
        int d0 = ch * 64;
        __syncthreads();
#pragma unroll
        for (int it = 0; it < 16; it++) {            // A = V chunk (KM)
            int idx = it * 512 + tid;
            int kd = idx >> 7, p = idx & 127;
            A2[kd * PKM + p] = split2(V[(size_t)(d0 + kd) * HWN + n0 + p]);
        }
#pragma unroll
        for (int it = 0; it < 16; it++) {            // B = S chunk (MK)
            int idx = it * 512 + tid;
            int cc = idx >> 6, kd = idx & 63;
            B2[cc * PMK + kd] = split2(S[cc * CN + d0 + kd]);
        }
        __syncthreads();
        gemm64<true, false>(A2, B2, c4, m0, n0w, r, q);
    }

    float* Out = g_A + (size_t)att * BCHWN + (size_t)b * CHWN;
#pragma unroll
    for (int mi = 0; mi < 2; mi++) {
        int p0r = m0 + mi * 16 + r;
#pragma unroll
        for (int ni = 0; ni < 4; ni++) {
            int col = n0w + ni * 8 + 2 * q;
            Out[(size_t)col * HWN + n0 + p0r]           = c4[mi][ni][0];
            Out[(size_t)(col + 1) * HWN + n0 + p0r]     = c4[mi][ni][1];
            Out[(size_t)col * HWN + n0 + p0r + 8]       = c4[mi][ni][2];
            Out[(size_t)(col + 1) * HWN + n0 + p0r + 8] = c4[mi][ni][3];
        }
    }
}

// ---------------- kernel 6: final linear ----------------
// C[pix][co] = sum_t flat[pix][t] lw[co][t];  A=flat (MK), B=lw (MK)
__global__ __launch_bounds__(512, 1) void k_final(const float* __restrict__ lw,
                                                  const float* __restrict__ lb) {
    extern __shared__ char smraw[];
    uint2* A2 = (uint2*)smraw;
    uint2* B2 = (uint2*)(smraw + TILE_BYTES);
    int tid = threadIdx.x, wid = tid >> 5, lane = tid & 31;
    int nt = blockIdx.x, b = blockIdx.y;
    int n0 = nt * 128;

    int m0 = (wid & 3) * 32, n0w = (wid >> 2) * 32;
    int r = lane >> 2, q = lane & 3;
    float c4[2][4][4];
    ZERO_C(c4);

    for (int ch = 0; ch < 4; ch++) {
        int part = ch >> 1, t0 = (ch & 1) * 64;
        const float* Abuf = g_A + (size_t)(part * BB + b) * CHWN + (size_t)n0 * CN;
        __syncthreads();
#pragma unroll
        for (int it = 0; it < 16; it++) {            // A = flat chunk (MK)
            int idx = it * 512 + tid;
            int p = idx >> 6, kt = idx & 63;
            A2[p * PMK + kt] = split2(Abuf[p * CN + t0 + kt]);
        }
#pragma unroll
        for (int it = 0; it < 16; it++) {            // B = lw chunk (MK)
            int idx = it * 512 + tid;
            int co = idx >> 6, kt = idx & 63;
            B2[co * PMK + kt] = split2(lw[co * 256 + part * 128 + t0 + kt]);
        }
        __syncthreads();
        gemm64<false, false>(A2, B2, c4, m0, n0w, r, q);
    }

    float* Ob = g_lin + (size_t)b * CHWN;
#pragma unroll
    for (int mi = 0; mi < 2; mi++) {
        int p0r = n0 + m0 + mi * 16 + r;
#pragma unroll
        for (int ni = 0; ni < 4; ni++) {
            int col = n0w + ni * 8 + 2 * q;
            float b0 = __ldg(&lb[col]), b1 = __ldg(&lb[col + 1]);
            Ob[(size_t)p0r * CN + col]           = c4[mi][ni][0] + b0;
            Ob[(size_t)p0r * CN + col + 1]       = c4[mi][ni][1] + b1;
            Ob[(size_t)(p0r + 8) * CN + col]     = c4[mi][ni][2] + b0;
            Ob[(size_t)(p0r + 8) * CN + col + 1] = c4[mi][ni][3] + b1;
        }
    }
}

// ---------------- kernel 7: tail transpose + residual ----------------
__global__ __launch_bounds__(256) void k_tail(const float* __restrict__ Fi,
                                              const float* __restrict__ Fw,
                                              float* __restrict__ out) {
    __shared__ float tile[32][33];
    int b  = blockIdx.z;
    int r0 = blockIdx.x * 32;
    int c0 = blockIdx.y * 32;
    const float* In = g_lin + (size_t)b * CHWN;
    int tx = threadIdx.x & 31, ty = threadIdx.x >> 5;
#pragma unroll
    for (int s2 = 0; s2 < 4; s2++) {
        int cc = c0 + ty + 8 * s2;
        tile[ty + 8 * s2][tx] = In[(size_t)cc * HWN + r0 + tx];
    }
    __syncthreads();
    size_t base = (size_t)b * CHWN;
#pragma unroll
    for (int s2 = 0; s2 < 4; s2++) {
        int r = r0 + ty + 8 * s2;
        size_t idx = base + (size_t)r * CN + c0 + tx;
        out[idx] = tile[tx][ty + 8 * s2] + Fi[idx] + Fw[idx];
    }
}

// ---------------- launch ----------------
extern "C" void kernel_launch(void* const* d_in, const int* in_sizes, int n_in,
                              void* d_out, int out_size) {
    const float* Fi = (const float*)d_in[0];
    const float* Fw = (const float*)d_in[1];
    const float* g1 = (const float*)d_in[2];
    const float* g2 = (const float*)d_in[3];

    const float *qw1, *kw1, *vw1, *qw2, *kw2, *vw2;
    const float *qb1, *kb1, *vb1, *qb2, *kb2, *vb2;
    const float *qdw1, *kdw1, *vdw1, *qdw2, *kdw2, *vdw2;
    const float *qdb1, *kdb1, *vdb1, *qdb2, *kdb2, *vdb2;
    const float *lw, *lb;

    if (in_sizes[5] == CN) {
        qw1 = (const float*)d_in[4];  qb1 = (const float*)d_in[5];
        kw1 = (const float*)d_in[6];  kb1 = (const float*)d_in[7];
        vw1 = (const float*)d_in[8];  vb1 = (const float*)d_in[9];
        qw2 = (const float*)d_in[10]; qb2 = (const float*)d_in[11];
        kw2 = (const float*)d_in[12]; kb2 = (const float*)d_in[13];
        vw2 = (const float*)d_in[14]; vb2 = (const float*)d_in[15];
        qdw1 = (const float*)d_in[16]; qdb1 = (const float*)d_in[17];
        kdw1 = (const float*)d_in[18]; kdb1 = (const float*)d_in[19];
        vdw1 = (const float*)d_in[20]; vdb1 = (const float*)d_in[21];
        qdw2 = (const float*)d_in[22]; qdb2 = (const float*)d_in[23];
        kdw2 = (const float*)d_in[24]; kdb2 = (const float*)d_in[25];
        vdw2 = (const float*)d_in[26]; vdb2 = (const float*)d_in[27];
    } else {
        qw1 = (const float*)d_in[4];  kw1 = (const float*)d_in[5];
        vw1 = (const float*)d_in[6];  qw2 = (const float*)d_in[7];
        kw2 = (const float*)d_in[8];  vw2 = (const float*)d_in[9];
        qb1 = (const float*)d_in[10]; kb1 = (const float*)d_in[11];
        vb1 = (const float*)d_in[12]; qb2 = (const float*)d_in[13];
        kb2 = (const float*)d_in[14]; vb2 = (const float*)d_in[15];
        qdw1 = (const float*)d_in[16]; kdw1 = (const float*)d_in[17];
        vdw1 = (const float*)d_in[18]; qdw2 = (const float*)d_in[19];
        kdw2 = (const float*)d_in[20]; vdw2 = (const float*)d_in[21];
        qdb1 = (const float*)d_in[22]; kdb1 = (const float*)d_in[23];
        vdb1 = (const float*)d_in[24]; qdb2 = (const float*)d_in[25];
        kdb2 = (const float*)d_in[26]; vdb2 = (const float*)d_in[27];
    }
    lw = (const float*)d_in[28];
    lb = (const float*)d_in[29];
    float* out = (float*)d_out;

    cudaFuncSetAttribute(k_ln_c11, cudaFuncAttributeMaxDynamicSharedMemorySize, SMEM_BYTES);
    cudaFuncSetAttribute(k_qk,     cudaFuncAttributeMaxDynamicSharedMemorySize, SMEM_BYTES);
    cudaFuncSetAttribute(k_av,     cudaFuncAttributeMaxDynamicSharedMemorySize, SMEM_BYTES);
    cudaFuncSetAttribute(k_final,  cudaFuncAttributeMaxDynamicSharedMemorySize, SMEM_BYTES);

    k_stats  <<<dim3(NPIX / 256, 2), 256>>>(Fi, Fw);
    k_ln_c11 <<<dim3(NPIX / 128, 2), 512, SMEM_BYTES>>>(Fi, Fw, g1, g2,
                                                        qw1, kw1, vw1, qb1, kb1, vb1,
                                                        qw2, kw2, vw2, qb2, kb2, vb2);
    k_dw     <<<dim3(CHWN / 256, BB, 6), 256>>>(qdw1, kdw1, vdw1, qdw2, kdw2, vdw2,
                                                qdb1, kdb1, vdb1, qdb2, kdb2, vdb2);
    k_qk     <<<dim3(NSPLIT, BB, 2), 512, SMEM_BYTES>>>();
    k_softmax<<<dim3(256), 256>>>();
    k_av     <<<dim3(HWN / 128, BB, 2), 512, SMEM_BYTES>>>();
    k_final  <<<dim3(HWN / 128, BB), 512, SMEM_BYTES>>>(lw, lb);
    k_tail   <<<dim3(HWN / 32, CN / 32, BB), 256>>>(Fi, Fw, out);
}

// round 10
// speedup vs baseline: 1.2792x; 1.1180x over previous
#include <cuda_runtime.h>
#include <cstdint>

// ---------------- problem constants ----------------
#define BB    8
#define CN    128
#define HN    128
#define WN    128
#define HWN   16384
#define CHWN  (CN*HWN)                 // 2,097,152
#define BCHWN (BB*CHWN)                // 16,777,216
#define NPIX  (BB*HWN)                 // 131,072
#define NSPLIT 16

// smem tile layouts (uint2 {tf32_hi, tf32_lo} elements):
//  KM: [k][m], 64 x 128, pitch PKM;  MK: [m][k], 128 x 64, pitch PMK
#define PKM 130
#define PMK 66
#define TILE_BYTES 67584               // max(128*66, 64*130)*8
#define SMEM_G  (2*TILE_BYTES + 1024)  // 2-tile kernels
#define SMEM_LN (3*TILE_BYTES + 1024)  // ln: A + 2 persistent B chunks

// ---------------- device scratch ----------------
__device__ float g_pre [6ull*BCHWN];                       // 402 MB
__device__ __align__(16) uint2 g_post2[6ull*BCHWN];        // 805 MB split
__device__ float g_Spart[2ull*NSPLIT*BB*CN*CN];            // 33 MB
__device__ __align__(16) uint2 g_S2[2ull*BB*CN*CN];        // 2 MB split
__device__ float g_A   [2ull*BCHWN];                       // 134 MB
__device__ float g_lin [1ull*BCHWN];                       // 67 MB
__device__ __align__(16) uint2 g_w2 [6*CN*CN];             // split 1x1 weights
__device__ __align__(16) uint2 g_lw2[2*CN*CN];             // split lw

__device__ float g_mean[2*NPIX];
__device__ float g_rstd[2*NPIX];

// ---------------- tf32 split + mma ----------------
__device__ __forceinline__ uint2 split2(float x) {
    uint32_t h;
    asm("cvt.rna.tf32.f32 %0, %1;" : "=r"(h) : "f"(x));
    float l = x - __uint_as_float(h);
    uint32_t lo;
    asm("cvt.rna.tf32.f32 %0, %1;" : "=r"(lo) : "f"(l));
    return make_uint2(h, lo);
}
__device__ __forceinline__ void mma8(float c[4], const uint32_t a[4],
                                     uint32_t b0, uint32_t b1) {
    asm volatile(
        "mma.sync.aligned.m16n8k8.row.col.f32.tf32.tf32.f32 "
        "{%0,%1,%2,%3},{%4,%5,%6,%7},{%8,%9},{%0,%1,%2,%3};"
        : "+f"(c[0]), "+f"(c[1]), "+f"(c[2]), "+f"(c[3])
        : "r"(a[0]), "r"(a[1]), "r"(a[2]), "r"(a[3]), "r"(b0), "r"(b1));
}

// C[128x128] += A * B^T over a 64-wide K chunk; warp tile 32(m) x 32(n).
template<bool AKM, bool BKM>
__device__ __forceinline__ void gemm64(const uint2* __restrict__ A2,
                                       const uint2* __restrict__ B2,
                                       float c4[2][4][4],
                                       int m0, int n0w, int r, int q) {
#pragma unroll
    for (int ks = 0; ks < 8; ks++) {
        int k0 = ks * 8;
        uint32_t ahi[2][4], alo[2][4];
#pragma unroll
        for (int mi = 0; mi < 2; mi++) {
            int m = m0 + mi * 16 + r;
            uint2 p0, p1, p2, p3;
            if (AKM) {
                p0 = A2[(k0 + q) * PKM + m];
                p1 = A2[(k0 + q) * PKM + m + 8];
                p2 = A2[(k0 + q + 4) * PKM + m];
                p3 = A2[(k0 + q + 4) * PKM + m + 8];
            } else {
                p0 = A2[m * PMK + k0 + q];
                p1 = A2[(m + 8) * PMK + k0 + q];
                p2 = A2[m * PMK + k0 + q + 4];
                p3 = A2[(m + 8) * PMK + k0 + q + 4];
            }
            ahi[mi][0] = p0.x; ahi[mi][1] = p1.x; ahi[mi][2] = p2.x; ahi[mi][3] = p3.x;
            alo[mi][0] = p0.y; alo[mi][1] = p1.y; alo[mi][2] = p2.y; alo[mi][3] = p3.y;
        }
#pragma unroll
        for (int ni = 0; ni < 4; ni++) {
            int col = n0w + ni * 8 + r;
            uint2 pb0, pb1;
            if (BKM) {
                pb0 = B2[(k0 + q) * PKM + col];
                pb1 = B2[(k0 + q + 4) * PKM + col];
            } else {
                pb0 = B2[col * PMK + k0 + q];
                pb1 = B2[col * PMK + k0 + q + 4];
            }
#pragma unroll
            for (int mi = 0; mi < 2; mi++) {
                mma8(c4[mi][ni], ahi[mi], pb0.x, pb1.x);
                mma8(c4[mi][ni], alo[mi], pb0.x, pb1.x);
                mma8(c4[mi][ni], ahi[mi], pb0.y, pb1.y);
            }
        }
    }
}
#define ZERO_C(c4) {                                   \
    _Pragma("unroll") for (int mi = 0; mi < 2; mi++)   \
    _Pragma("unroll") for (int ni = 0; ni < 4; ni++)   \
    _Pragma("unroll") for (int t = 0; t < 4; t++) (c4)[mi][ni][t] = 0.f; }

// ---------------- kernel 0: LayerNorm stats per pixel ----------------
__global__ __launch_bounds__(256) void k_stats(const float* __restrict__ Fi,
                                               const float* __restrict__ Fw) {
    int inp = blockIdx.y;
    const float* X = inp ? Fw : Fi;
    int p = blockIdx.x * 256 + threadIdx.x;
    int b = p >> 14, pix = p & (HWN - 1);
    const float* Xb = X + (size_t)b * CHWN + pix;
    float s = 0.f, ss = 0.f;
#pragma unroll 8
    for (int c = 0; c < CN; c++) {
        float v = Xb[(size_t)c * HWN];
        s += v; ss += v * v;
    }
    float m = s * (1.f / CN);
    float var = ss * (1.f / CN) - m * m;
    g_mean[inp * NPIX + p] = m;
    g_rstd[inp * NPIX + p] = rsqrtf(var + 1e-5f);
}

// ---------------- kernel 0b: pre-split weights ----------------
__global__ __launch_bounds__(256) void k_splitw(
    const float* w0, const float* w1, const float* w2,
    const float* w3, const float* w4, const float* w5,
    const float* lw) {
    int i = blockIdx.x * 256 + threadIdx.x;            // 131072 total
    if (i < 6 * CN * CN) {
        const float* srcs[6] = {w0, w1, w2, w3, w4, w5};
        g_w2[i] = split2(srcs[i >> 14][i & 16383]);
    } else {
        int j = i - 6 * CN * CN;
        g_lw2[j] = split2(lw[j]);
    }
}

// ---------------- kernel 1: fused LN + 3x(1x1 conv) ----------------
// C[o][pix] = sum_c W[o][c] * Xn[pix][c];  A=W (MK, copy), B=Xn (KM, split once)
__global__ __launch_bounds__(512, 1) void k_ln_c11(
    const float* __restrict__ Fi, const float* __restrict__ Fw,
    const float* __restrict__ g1, const float* __restrict__ g2,
    const float* bq, const float* bk, const float* bv,
    const float* bq2, const float* bk2, const float* bv2) {
    extern __shared__ char smraw[];
    uint2* A2  = (uint2*)smraw;
    uint2* B2a = (uint2*)(smraw + TILE_BYTES);
    uint2* B2b = (uint2*)(smraw + 2 * TILE_BYTES);
    float* mu_s = (float*)(smraw + 3 * TILE_BYTES);
    float* rs_s = mu_s + 128;

    int tid = threadIdx.x, wid = tid >> 5, lane = tid & 31;
    int inp = blockIdx.y;
    int p0 = blockIdx.x * 128;
    int b = p0 >> 14, pix0 = p0 & (HWN - 1);
    const float* X = inp ? Fw : Fi;
    const float* gamma = inp ? g2 : g1;
    const float* Bs3[3] = { inp ? bq2 : bq, inp ? bk2 : bk, inp ? bv2 : bv };

    if (tid < 128) {
        mu_s[tid] = g_mean[inp * NPIX + p0 + tid];
        rs_s[tid] = g_rstd[inp * NPIX + p0 + tid];
    }
    __syncthreads();

    // stage Xn once (both 64-chunks, KM layout, split here)
    const float* Xb = X + (size_t)b * CHWN + pix0;
#pragma unroll 2
    for (int ch2 = 0; ch2 < 2; ch2++) {
        uint2* Bt = ch2 ? B2b : B2a;
        int c0 = ch2 * 64;
#pragma unroll
        for (int it = 0; it < 16; it++) {
            int idx = it * 512 + tid;
            int kc = idx >> 7, p = idx & 127;
            float v = Xb[(size_t)(c0 + kc) * HWN + p];
            Bt[kc * PKM + p] = split2((v - mu_s[p]) * rs_s[p] * __ldg(&gamma[c0 + kc]));
        }
    }

    int m0 = (wid & 3) * 32, n0w = (wid >> 2) * 32;
    int r = lane >> 2, q = lane & 3;

    for (int i = 0; i < 3; i++) {
        const uint2* Wsrc = g_w2 + (size_t)(inp * 3 + i) * CN * CN;
        float c4[2][4][4];
        ZERO_C(c4);
#pragma unroll 2
        for (int ch = 0; ch < 2; ch++) {
            __syncthreads();
#pragma unroll
            for (int it = 0; it < 8; it++) {           // A = W chunk (MK, copy)
                int idx = (it * 512 + tid) * 2;
                int o = idx >> 6, kc = idx & 63;
                *(uint4*)(A2 + o * PMK + kc) =
                    *(const uint4*)(Wsrc + o * CN + ch * 64 + kc);
            }
            __syncthreads();
            gemm64<false, true>(A2, ch ? B2b : B2a, c4, m0, n0w, r, q);
        }
        // transpose epilogue via smem (reuse A2 region), coalesced STG
        __syncthreads();
        float* T = (float*)smraw;                      // pitch 131
#pragma unroll
        for (int mi = 0; mi < 2; mi++) {
            int o0 = m0 + mi * 16 + r;
#pragma unroll
            for (int ni = 0; ni < 4; ni++) {
                int col = n0w + ni * 8 + 2 * q;
                T[o0 * 131 + col]           = c4[mi][ni][0];
                T[o0 * 131 + col + 1]       = c4[mi][ni][1];
                T[(o0 + 8) * 131 + col]     = c4[mi][ni][2];
                T[(o0 + 8) * 131 + col + 1] = c4[mi][ni][3];
            }
        }
        __syncthreads();
        const float* bias = Bs3[i];
        float* Ob = g_pre + ((size_t)(inp * 3 + i) * BB + b) * CHWN;
        int orow = wid * 8;
#pragma unroll
        for (int rr = 0; rr < 8; rr++) {
            int o = orow + rr;
            float bo = __ldg(&bias[o]);
#pragma unroll
            for (int j = 0; j < 4; j++)
                Ob[(size_t)o * HWN + pix0 + lane + 32 * j] =
                    T[o * 131 + lane + 32 * j] + bo;
        }
    }
}

// ---------------- kernel 2: depthwise 3x3 -> split pairs ----------------
__global__ __launch_bounds__(256) void k_dw(
    const float* d0, const float* d1, const float* d2,
    const float* d3, const float* d4, const float* d5,
    const float* e0, const float* e1, const float* e2,
    const float* e3, const float* e4, const float* e5) {
    int br = blockIdx.z, b = blockIdx.y;
    int e = blockIdx.x * 256 + threadIdx.x;
    int c = e >> 14, pix = e & (HWN - 1);
    int h = pix >> 7, w = pix & 127;
    const float* Wd6[6] = {d0, d1, d2, d3, d4, d5};
    const float* Bd6[6] = {e0, e1, e2, e3, e4, e5};
    const float* Wd = Wd6[br] + c * 9;
    const float* In = g_pre + (size_t)br * BCHWN + (size_t)b * CHWN + (size_t)c * HWN;
    float acc = __ldg(&Bd6[br][c]);
#pragma unroll
    for (int dy = -1; dy <= 1; dy++) {
        int hh = h + dy;
        if ((unsigned)hh < (unsigned)HN) {
            const float* row = In + hh * WN;
#pragma unroll
            for (int dx = -1; dx <= 1; dx++) {
                int ww = w + dx;
                if ((unsigned)ww < (unsigned)WN)
                    acc += __ldg(&Wd[(dy + 1) * 3 + (dx + 1)]) * row[ww];
            }
        }
    }
    g_post2[(size_t)br * BCHWN + (size_t)b * CHWN + e] = split2(acc);
}

// ---------------- kernel 3: S partials (copy-only staging) ----------------
// C[c][d] = sum_n Q[n][c] K[n][d];  A=Q (KM), B=K (KM)
__global__ __launch_bounds__(512, 1) void k_qk() {
    extern __shared__ char smraw[];
    uint2* A2 = (uint2*)smraw;
    uint2* B2 = (uint2*)(smraw + TILE_BYTES);
    int tid = threadIdx.x, wid = tid >> 5, lane = tid & 31;
    int s = blockIdx.x, b = blockIdx.y, att = blockIdx.z;
    const uint2* Q2 = g_post2 + (size_t)(att == 0 ? 0 : 3) * BCHWN + (size_t)b * CHWN;
    const uint2* K2 = g_post2 + (size_t)(att == 0 ? 4 : 1) * BCHWN + (size_t)b * CHWN;

    int m0 = (wid & 3) * 32, n0w = (wid >> 2) * 32;
    int r = lane >> 2, q = lane & 3;
    float c4[2][4][4];
    ZERO_C(c4);

    for (int ch = 0; ch < 16; ch++) {
        size_t nbase = (size_t)(s * 1024 + ch * 64) * CN;
        __syncthreads();
#pragma unroll
        for (int it = 0; it < 8; it++) {
            int idx = (it * 512 + tid) * 2;
            int nn = idx >> 7, cc = idx & 127;
            *(uint4*)(A2 + nn * PKM + cc) = *(const uint4*)(Q2 + nbase + nn * CN + cc);
            *(uint4*)(B2 + nn * PKM + cc) = *(const uint4*)(K2 + nbase + nn * CN + cc);
        }
        __syncthreads();
        gemm64<true, true>(A2, B2, c4, m0, n0w, r, q);
    }

    float* Sp = g_Spart + ((size_t)(att * NSPLIT + s) * BB + b) * (CN * CN);
#pragma unroll
    for (int mi = 0; mi < 2; mi++) {
        int c0 = m0 + mi * 16 + r;
#pragma unroll
        for (int ni = 0; ni < 4; ni++) {
            int col = n0w + ni * 8 + 2 * q;
            *(float2*)&Sp[c0 * CN + col] = make_float2(c4[mi][ni][0], c4[mi][ni][1]);
            *(float2*)&Sp[(c0 + 8) * CN + col] = make_float2(c4[mi][ni][2], c4[mi][ni][3]);
        }
    }
}

// ---------------- kernel 4: reduce partials + softmax -> split ----------------
__global__ __launch_bounds__(256) void k_softmax() {
    int row  = blockIdx.x * 8 + (threadIdx.x >> 5);
    int lane = threadIdx.x & 31;
    int att = row >> 10, rb = row & 1023, b = rb >> 7, c = rb & 127;
    float v[4];
#pragma unroll
    for (int q = 0; q < 4; q++) {
        int d = lane + 32 * q;
        float s = 0.f;
        for (int sp = 0; sp < NSPLIT; sp++)
            s += g_Spart[((size_t)(att * NSPLIT + sp) * BB + b) * (CN * CN) + c * CN + d];
        v[q] = s;
    }
    float mx = fmaxf(fmaxf(v[0], v[1]), fmaxf(v[2], v[3]));
#pragma unroll
    for (int o = 16; o > 0; o >>= 1) mx = fmaxf(mx, __shfl_xor_sync(0xffffffffu, mx, o));
    float e[4], sum = 0.f;
#pragma unroll
    for (int q = 0; q < 4; q++) { e[q] = __expf(v[q] - mx); sum += e[q]; }
#pragma unroll
    for (int o = 16; o > 0; o >>= 1) sum += __shfl_xor_sync(0xffffffffu, sum, o);
    float inv = 1.f / sum;
#pragma unroll
    for (int q = 0; q < 4; q++)
        g_S2[(size_t)(att * BB + b) * (CN * CN) + c * CN + lane + 32 * q] =
            split2(e[q] * inv);
}

// ---------------- kernel 5: A@V (copy staging, transposed epilogue) ----------
// C[npix][c] = sum_d V[d][n0+npix] * S[c][d];  A=V (KM), B=S (MK)
__global__ __launch_bounds__(512, 1) void k_av() {
    extern __shared__ char smraw[];
    uint2* A2 = (uint2*)smraw;
    uint2* B2 = (uint2*)(smraw + TILE_BYTES);
    int tid = threadIdx.x, wid = tid >> 5, lane = tid & 31;
    int nt = blockIdx.x, b = blockIdx.y, att = blockIdx.z;
    const uint2* S2 = g_S2 + (size_t)(att * BB + b) * (CN * CN);
    const uint2* V2 = g_post2 + (size_t)(att == 0 ? 5 : 2) * BCHWN + (size_t)b * CHWN;
    int n0 = nt * 128;

    int m0 = (wid & 3) * 32, n0w = (wid >> 2) * 32;
    int r = lane >> 2, q = lane & 3;
    float c4[2][4][4];
    ZERO_C(c4);

#pragma unroll 2
    for (int ch = 0; ch < 2; ch++) {
        int d0 = ch * 64;
        __syncthreads();
#pragma unroll
        for (int it = 0; it < 8; it++) {               // A = V chunk (KM)
            int idx = (it * 512 + tid) * 2;
            int kd = idx >> 7, p = idx & 127;
            *(uint4*)(A2 + kd * PKM + p) =
                *(const uint4*)(V2 + (size_t)(d0 + kd) * HWN + n0 + p);
        }
#pragma unroll
        for (int it = 0; it < 8; it++) {               // B = S chunk (MK)
            int idx = (it * 512 + tid) * 2;
            int cc = idx >> 6, kd = idx & 63;
            *(uint4*)(B2 + cc * PMK + kd) =
                *(const uint4*)(S2 + cc * CN + d0 + kd);
        }
        __syncthreads();
        gemm64<true, false>(A2, B2, c4, m0, n0w, r, q);
    }

    // transpose epilogue: T[c][n], then coalesced rows
    __syncthreads();
    float* T = (float*)smraw;                          // pitch 131
#pragma unroll
    for (int mi = 0; mi < 2; mi++) {
        int rr = m0 + mi * 16 + r;                     // n index
#pragma unroll
        for (int ni = 0; ni < 4; ni++) {
            int cc = n0w + ni * 8 + 2 * q;             // c index
            T[cc * 131 + rr]           = c4[mi][ni][0];
            T[(cc + 1) * 131 + rr]     = c4[mi][ni][1];
            T[cc * 131 + rr + 8]       = c4[mi][ni][2];
            T[(cc + 1) * 131 + rr + 8] = c4[mi][ni][3];
        }
    }
    __syncthreads();
    float* Out = g_A + (size_t)att * BCHWN + (size_t)b * CHWN;
    int crow = wid * 8;
#pragma unroll
    for (int rr = 0; rr < 8; rr++) {
        int cc = crow + rr;
#pragma unroll
        for (int j = 0; j < 4; j++)
            Out[(size_t)cc * HWN + n0 + lane + 32 * j] = T[cc * 131 + lane + 32 * j];
    }
}

// ---------------- kernel 6: final linear ----------------
// C[pix][co] = sum_t flat[pix][t] lw[co][t];  A=flat (MK, split here), B=lw2 (copy)
__global__ __launch_bounds__(512, 1) void k_final(const float* __restrict__ lb) {
    extern __shared__ char smraw[];
    uint2* A2 = (uint2*)smraw;
    uint2* B2 = (uint2*)(smraw + TILE_BYTES);
    int tid = threadIdx.x, wid = tid >> 5, lane = tid & 31;
    int nt = blockIdx.x, b = blockIdx.y;
    int n0 = nt * 128;

    int m0 = (wid & 3) * 32, n0w = (wid >> 2) * 32;
    int r = lane >> 2, q = lane & 3;
    float c4[2][4][4];
    ZERO_C(c4);

    for (int ch = 0; ch < 4; ch++) {
        int part = ch >> 1, t0 = (ch & 1) * 64;
        const float* Abuf = g_A + (size_t)(part * BB + b) * CHWN + (size_t)n0 * CN;
        __syncthreads();
#pragma unroll
        for (int it = 0; it < 16; it++) {              // A = flat chunk (MK, split)
            int idx = it * 512 + tid;
            int p = idx >> 6, kt = idx & 63;
            A2[p * PMK + kt] = split2(Abuf[p * CN + t0 + kt]);
        }
#pragma unroll
        for (int it = 0; it < 8; it++) {               // B = lw chunk (MK, copy)
            int idx = (it * 512 + tid) * 2;
            int co = idx >> 6, kt = idx & 63;
            *(uint4*)(B2 + co * PMK + kt) =
                *(const uint4*)(g_lw2 + co * 256 + part * 128 + t0 + kt);
        }
        __syncthreads();
        gemm64<false, false>(A2, B2, c4, m0, n0w, r, q);
    }

    float* Ob = g_lin + (size_t)b * CHWN;
#pragma unroll
    for (int mi = 0; mi < 2; mi++) {
        int p0r = n0 + m0 + mi * 16 + r;
#pragma unroll
        for (int ni = 0; ni < 4; ni++) {
            int col = n0w + ni * 8 + 2 * q;
            float b0 = __ldg(&lb[col]), b1 = __ldg(&lb[col + 1]);
            *(float2*)&Ob[(size_t)p0r * CN + col] =
                make_float2(c4[mi][ni][0] + b0, c4[mi][ni][1] + b1);
            *(float2*)&Ob[(size_t)(p0r + 8) * CN + col] =
                make_float2(c4[mi][ni][2] + b0, c4[mi][ni][3] + b1);
        }
    }
}

// ---------------- kernel 7: tail transpose + residual ----------------
__global__ __launch_bounds__(256) void k_tail(const float* __restrict__ Fi,
                                              const float* __restrict__ Fw,
                                              float* __restrict__ out) {
    __shared__ float tile[32][33];
    int b  = blockIdx.z;
    int r0 = blockIdx.x * 32;
    int c0 = blockIdx.y * 32;
    const float* In = g_lin + (size_t)b * CHWN;
    int tx = threadIdx.x & 31, ty = threadIdx.x >> 5;
#pragma unroll
    for (int s2 = 0; s2 < 4; s2++) {
        int cc = c0 + ty + 8 * s2;
        tile[ty + 8 * s2][tx] = In[(size_t)cc * HWN + r0 + tx];
    }
    __syncthreads();
    size_t base = (size_t)b * CHWN;
#pragma unroll
    for (int s2 = 0; s2 < 4; s2++) {
        int r = r0 + ty + 8 * s2;
        size_t idx = base + (size_t)r * CN + c0 + tx;
        out[idx] = tile[tx][ty + 8 * s2] + Fi[idx] + Fw[idx];
    }
}

// ---------------- launch ----------------
extern "C" void kernel_launch(void* const* d_in, const int* in_sizes, int n_in,
                              void* d_out, int out_size) {
    const float* Fi = (const float*)d_in[0];
    const float* Fw = (const float*)d_in[1];
    const float* g1 = (const float*)d_in[2];
    const float* g2 = (const float*)d_in[3];

    const float *qw1, *kw1, *vw1, *qw2, *kw2, *vw2;
    const float *qb1, *kb1, *vb1, *qb2, *kb2, *vb2;
    const float *qdw1, *kdw1, *vdw1, *qdw2, *kdw2, *vdw2;
    const float *qdb1, *kdb1, *vdb1, *qdb2, *kdb2, *vdb2;
    const float *lw, *lb;

    if (in_sizes[5] == CN) {
        qw1 = (const float*)d_in[4];  qb1 = (const float*)d_in[5];
        kw1 = (const float*)d_in[6];  kb1 = (const float*)d_in[7];
        vw1 = (const float*)d_in[8];  vb1 = (const float*)d_in[9];
        qw2 = (const float*)d_in[10]; qb2 = (const float*)d_in[11];
        kw2 = (const float*)d_in[12]; kb2 = (const float*)d_in[13];
        vw2 = (const float*)d_in[14]; vb2 = (const float*)d_in[15];
        qdw1 = (const float*)d_in[16]; qdb1 = (const float*)d_in[17];
        kdw1 = (const float*)d_in[18]; kdb1 = (const float*)d_in[19];
        vdw1 = (const float*)d_in[20]; vdb1 = (const float*)d_in[21];
        qdw2 = (const float*)d_in[22]; qdb2 = (const float*)d_in[23];
        kdw2 = (const float*)d_in[24]; kdb2 = (const float*)d_in[25];
        vdw2 = (const float*)d_in[26]; vdb2 = (const float*)d_in[27];
    } else {
        qw1 = (const float*)d_in[4];  kw1 = (const float*)d_in[5];
        vw1 = (const float*)d_in[6];  qw2 = (const float*)d_in[7];
        kw2 = (const float*)d_in[8];  vw2 = (const float*)d_in[9];
        qb1 = (const float*)d_in[10]; kb1 = (const float*)d_in[11];
        vb1 = (const float*)d_in[12]; qb2 = (const float*)d_in[13];
        kb2 = (const float*)d_in[14]; vb2 = (const float*)d_in[15];
        qdw1 = (const float*)d_in[16]; kdw1 = (const float*)d_in[17];
        vdw1 = (const float*)d_in[18]; qdw2 = (const float*)d_in[19];
        kdw2 = (const float*)d_in[20]; vdw2 = (const float*)d_in[21];
        qdb1 = (const float*)d_in[22]; kdb1 = (const float*)d_in[23];
        vdb1 = (const float*)d_in[24]; qdb2 = (const float*)d_in[25];
        kdb2 = (const float*)d_in[26]; vdb2 = (const float*)d_in[27];
    }
    lw = (const float*)d_in[28];
    lb = (const float*)d_in[29];
    float* out = (float*)d_out;

    cudaFuncSetAttribute(k_ln_c11, cudaFuncAttributeMaxDynamicSharedMemorySize, SMEM_LN);
    cudaFuncSetAttribute(k_qk,     cudaFuncAttributeMaxDynamicSharedMemorySize, SMEM_G);
    cudaFuncSetAttribute(k_av,     cudaFuncAttributeMaxDynamicSharedMemorySize, SMEM_G);
    cudaFuncSetAttribute(k_final,  cudaFuncAttributeMaxDynamicSharedMemorySize, SMEM_G);

    k_stats  <<<dim3(NPIX / 256, 2), 256>>>(Fi, Fw);
    k_splitw <<<dim3(512), 256>>>(qw1, kw1, vw1, qw2, kw2, vw2, lw);
    k_ln_c11 <<<dim3(NPIX / 128, 2), 512, SMEM_LN>>>(Fi, Fw, g1, g2,
                                                     qb1, kb1, vb1, qb2, kb2, vb2);
    k_dw     <<<dim3(CHWN / 256, BB, 6), 256>>>(qdw1, kdw1, vdw1, qdw2, kdw2, vdw2,
                                                qdb1, kdb1, vdb1, qdb2, kdb2, vdb2);
    k_qk     <<<dim3(NSPLIT, BB, 2), 512, SMEM_G>>>();
    k_softmax<<<dim3(256), 256>>>();
    k_av     <<<dim3(HWN / 128, BB, 2), 512, SMEM_G>>>();
    k_final  <<<dim3(HWN / 128, BB), 512, SMEM_G>>>(lb);
    k_tail   <<<dim3(HWN / 32, CN / 32, BB), 256>>>(Fi, Fw, out);
}

// round 13
// speedup vs baseline: 2.1963x; 1.7170x over previous
#include <cuda_runtime.h>
#include <cuda_bf16.h>
#include <cstdint>

// ---------------- problem constants ----------------
#define BB    8
#define CN    128
#define HN    128
#define WN    128
#define HWN   16384
#define CHWN  (CN*HWN)                 // 2,097,152
#define BCHWN (BB*CHWN)                // 16,777,216
#define NPIX  (BB*HWN)                 // 131,072
#define NSPLIT 16

// tf32 smem layouts (uint2 {tf32_hi, tf32_lo}):
#define PKM 130                        // KM: [k][m] pitch (uint2)
#define PMK 66                         // MK: [m][k] pitch (uint2)
#define TILE_BYTES 67584               // ln tiles (K=64 chunks)
#define SMEM_LN (3*TILE_BYTES + 1024)
// qk: K=32 chunks, KM pitch 130
#define QK_TILE (32*130*8)             // 33280
#define SMEM_QK (2*QK_TILE + 512)
// bf16 pair layout: [k2][m] of uint2 {hi_bf16x2, lo_bf16x2}, pitch 131
#define PB 131
#define BF_TILE (32*PB*8)              // 33568
#define SMEM_BF (2*BF_TILE + 512)

// ---------------- device scratch ----------------
__device__ float g_pre [6ull*BCHWN];                        // conv1x1 out (fp32)
__device__ __align__(16) uint2    g_post2[4ull*BCHWN];      // dw out Q/K (tf32 pairs)
__device__ __align__(16) uint32_t g_postv[2ull*BCHWN];      // dw out V (bf16 packed)
__device__ float g_Spart[2ull*NSPLIT*BB*CN*CN];
__device__ __align__(16) uint32_t g_S2[2ull*BB*CN*CN];      // softmax (bf16 packed)
__device__ __align__(16) uint32_t g_A [2ull*BCHWN];         // attn out (bf16 packed)
__device__ float g_lin [1ull*BCHWN];
__device__ __align__(16) uint2    g_w2 [6*CN*CN];           // 1x1 W (tf32 pairs)
__device__ __align__(16) uint32_t g_lw2b[2*CN*CN];          // lw (bf16 packed)
__device__ float g_mean[2*NPIX];
__device__ float g_rstd[2*NPIX];

// ---------------- splits ----------------
__device__ __forceinline__ uint2 split2(float x) {          // tf32 hi/lo
    uint32_t h;
    asm("cvt.rna.tf32.f32 %0, %1;" : "=r"(h) : "f"(x));
    float l = x - __uint_as_float(h);
    uint32_t lo;
    asm("cvt.rna.tf32.f32 %0, %1;" : "=r"(lo) : "f"(l));
    return make_uint2(h, lo);
}
__device__ __forceinline__ uint32_t bsplit(float x) {       // bf16 hi/lo packed
    __nv_bfloat16 h = __float2bfloat16(x);
    float l = x - __bfloat162float(h);
    __nv_bfloat16 lo = __float2bfloat16(l);
    return ((uint32_t)__bfloat16_as_ushort(lo) << 16) |
           (uint32_t)__bfloat16_as_ushort(h);
}

// ---------------- mma wrappers ----------------
__device__ __forceinline__ void mma8(float c[4], const uint32_t a[4],
                                     uint32_t b0, uint32_t b1) {
    asm volatile(
        "mma.sync.aligned.m16n8k8.row.col.f32.tf32.tf32.f32 "
        "{%0,%1,%2,%3},{%4,%5,%6,%7},{%8,%9},{%0,%1,%2,%3};"
        : "+f"(c[0]), "+f"(c[1]), "+f"(c[2]), "+f"(c[3])
        : "r"(a[0]), "r"(a[1]), "r"(a[2]), "r"(a[3]), "r"(b0), "r"(b1));
}
__device__ __forceinline__ void mmabf(float c[4], const uint32_t a[4],
                                      uint32_t b0, uint32_t b1) {
    asm volatile(
        "mma.sync.aligned.m16n8k16.row.col.f32.bf16.bf16.f32 "
        "{%0,%1,%2,%3},{%4,%5,%6,%7},{%8,%9},{%0,%1,%2,%3};"
        : "+f"(c[0]), "+f"(c[1]), "+f"(c[2]), "+f"(c[3])
        : "r"(a[0]), "r"(a[1]), "r"(a[2]), "r"(a[3]), "r"(b0), "r"(b1));
}

#define ZERO_C44(c4) {                                 \
    _Pragma("unroll") for (int mi = 0; mi < 2; mi++)   \
    _Pragma("unroll") for (int ni = 0; ni < 4; ni++)   \
    _Pragma("unroll") for (int t = 0; t < 4; t++) (c4)[mi][ni][t] = 0.f; }
#define ZERO_C48(c4) {                                 \
    _Pragma("unroll") for (int mi = 0; mi < 2; mi++)   \
    _Pragma("unroll") for (int ni = 0; ni < 8; ni++)   \
    _Pragma("unroll") for (int t = 0; t < 4; t++) (c4)[mi][ni][t] = 0.f; }

// tf32 KM/KM, K=32 chunk, warp tile 32x64 (ni=8) — for qk
__device__ __forceinline__ void gemm32t(const uint2* __restrict__ A2,
                                        const uint2* __restrict__ B2,
                                        float c4[2][8][4],
                                        int m0, int n0w, int r, int q) {
#pragma unroll
    for (int ks = 0; ks < 4; ks++) {
        int k0 = ks * 8;
        uint32_t ah[2][4], al[2][4];
#pragma unroll
        for (int mi = 0; mi < 2; mi++) {
            int m = m0 + mi * 16 + r;
            uint2 p0 = A2[(k0 + q) * PKM + m];
            uint2 p1 = A2[(k0 + q) * PKM + m + 8];
            uint2 p2 = A2[(k0 + q + 4) * PKM + m];
            uint2 p3 = A2[(k0 + q + 4) * PKM + m + 8];
            ah[mi][0] = p0.x; ah[mi][1] = p1.x; ah[mi][2] = p2.x; ah[mi][3] = p3.x;
            al[mi][0] = p0.y; al[mi][1] = p1.y; al[mi][2] = p2.y; al[mi][3] = p3.y;
        }
#pragma unroll
        for (int ni = 0; ni < 8; ni++) {
            int col = n0w + ni * 8 + r;
            uint2 v0 = B2[(k0 + q) * PKM + col];
            uint2 v1 = B2[(k0 + q + 4) * PKM + col];
#pragma unroll
            for (int mi = 0; mi < 2; mi++) {
                mma8(c4[mi][ni], ah[mi], v0.x, v1.x);
                mma8(c4[mi][ni], al[mi], v0.x, v1.x);
                mma8(c4[mi][ni], ah[mi], v0.y, v1.y);
            }
        }
    }
}

// bf16 pair KM/KM, K=64 chunk (32 k2-rows), warp tile 32x64 — for av/final
__device__ __forceinline__ void gemm_bf(const uint2* __restrict__ A2,
                                        const uint2* __restrict__ B2,
                                        float c4[2][8][4],
                                        int m0, int n0w, int r, int q) {
#pragma unroll
    for (int ks = 0; ks < 4; ks++) {
        int k2a = ks * 8 + q, k2b = ks * 8 + q + 4;
        uint32_t ah[2][4], al[2][4];
#pragma unroll
        for (int mi = 0; mi < 2; mi++) {
            int m = m0 + mi * 16 + r;
            uint2 u0 = A2[k2a * PB + m];
            uint2 u1 = A2[k2a * PB + m + 8];
            uint2 u2 = A2[k2b * PB + m];
            uint2 u3 = A2[k2b * PB + m + 8];
            ah[mi][0] = u0.x; ah[mi][1] = u1.x; ah[mi][2] = u2.x; ah[mi][3] = u3.x;
            al[mi][0] = u0.y; al[mi][1] = u1.y; al[mi][2] = u2.y; al[mi][3] = u3.y;
        }
#pragma unroll
        for (int ni = 0; ni < 8; ni++) {
            int col = n0w + ni * 8 + r;
            uint2 v0 = B2[k2a * PB + col];
            uint2 v1 = B2[k2b * PB + col];
#pragma unroll
            for (int mi = 0; mi < 2; mi++) {
                mmabf(c4[mi][ni], ah[mi], v0.x, v1.x);
                mmabf(c4[mi][ni], al[mi], v0.x, v1.x);
                mmabf(c4[mi][ni], ah[mi], v0.y, v1.y);
            }
        }
    }
}

// tf32 gemm for ln (A=MK pitch 66, B=KM pitch 130, K=64, 16 warps 32x32)
template<bool AKM, bool BKM>
__device__ __forceinline__ void gemm64(const uint2* __restrict__ A2,
                                       const uint2* __restrict__ B2,
                                       float c4[2][4][4],
                                       int m0, int n0w, int r, int q) {
#pragma unroll
    for (int ks = 0; ks < 8; ks++) {
        int k0 = ks * 8;
        uint32_t ah[2][4], al[2][4];
#pragma unroll
        for (int mi = 0; mi < 2; mi++) {
            int m = m0 + mi * 16 + r;
            uint2 p0, p1, p2, p3;
            if (AKM) {
                p0 = A2[(k0 + q) * PKM + m];
                p1 = A2[(k0 + q) * PKM + m + 8];
                p2 = A2[(k0 + q + 4) * PKM + m];
                p3 = A2[(k0 + q + 4) * PKM + m + 8];
            } else {
                p0 = A2[m * PMK + k0 + q];
                p1 = A2[(m + 8) * PMK + k0 + q];
                p2 = A2[m * PMK + k0 + q + 4];
                p3 = A2[(m + 8) * PMK + k0 + q + 4];
            }
            ah[mi][0] = p0.x; ah[mi][1] = p1.x; ah[mi][2] = p2.x; ah[mi][3] = p3.x;
            al[mi][0] = p0.y; al[mi][1] = p1.y; al[mi][2] = p2.y; al[mi][3] = p3.y;
        }
#pragma unroll
        for (int ni = 0; ni < 4; ni++) {
            int col = n0w + ni * 8 + r;
            uint2 v0, v1;
            if (BKM) {
                v0 = B2[(k0 + q) * PKM + col];
                v1 = B2[(k0 + q + 4) * PKM + col];
            } else {
                v0 = B2[col * PMK + k0 + q];
                v1 = B2[col * PMK + k0 + q + 4];
            }
#pragma unroll
            for (int mi = 0; mi < 2; mi++) {
                mma8(c4[mi][ni], ah[mi], v0.x, v1.x);
                mma8(c4[mi][ni], al[mi], v0.x, v1.x);
                mma8(c4[mi][ni], ah[mi], v0.y, v1.y);
            }
        }
    }
}

// ---------------- kernel 0: LayerNorm stats per pixel ----------------
__global__ __launch_bounds__(256) void k_stats(const float* __restrict__ Fi,
                                               const float* __restrict__ Fw) {
    int inp = blockIdx.y;
    const float* X = inp ? Fw : Fi;
    int p = blockIdx.x * 256 + threadIdx.x;
    int b = p >> 14, pix = p & (HWN - 1);
    const float* Xb = X + (size_t)b * CHWN + pix;
    float s = 0.f, ss = 0.f;
#pragma unroll 8
    for (int c = 0; c < CN; c++) {
        float v = Xb[(size_t)c * HWN];
        s += v; ss += v * v;
    }
    float m = s * (1.f / CN);
    float var = ss * (1.f / CN) - m * m;
    g_mean[inp * NPIX + p] = m;
    g_rstd[inp * NPIX + p] = rsqrtf(var + 1e-5f);
}

// ---------------- kernel 0b: pre-split weights ----------------
__global__ __launch_bounds__(256) void k_splitw(
    const float* w0, const float* w1, const float* w2,
    const float* w3, const float* w4, const float* w5,
    const float* lw) {
    int i = blockIdx.x * 256 + threadIdx.x;
    if (i < 6 * CN * CN) {
        const float* srcs[6] = {w0, w1, w2, w3, w4, w5};
        g_w2[i] = split2(srcs[i >> 14][i & 16383]);
    } else {
        int j = i - 6 * CN * CN;
        g_lw2b[j] = bsplit(lw[j]);
    }
}

// ---------------- kernel 1: fused LN + 3x(1x1 conv) (tf32x3) ----------
__global__ __launch_bounds__(512, 1) void k_ln_c11(
    const float* __restrict__ Fi, const float* __restrict__ Fw,
    const float* __restrict__ g1, const float* __restrict__ g2,
    const float* bq, const float* bk, const float* bv,
    const float* bq2, const float* bk2, const float* bv2) {
    extern __shared__ char smraw[];
    uint2* A2  = (uint2*)smraw;
    uint2* B2a = (uint2*)(smraw + TILE_BYTES);
    uint2* B2b = (uint2*)(smraw + 2 * TILE_BYTES);
    float* mu_s = (float*)(smraw + 3 * TILE_BYTES);
    float* rs_s = mu_s + 128;

    int tid = threadIdx.x, wid = tid >> 5, lane = tid & 31;
    int inp = blockIdx.y;
    int p0 = blockIdx.x * 128;
    int b = p0 >> 14, pix0 = p0 & (HWN - 1);
    const float* X = inp ? Fw : Fi;
    const float* gamma = inp ? g2 : g1;
    const float* Bs3[3] = { inp ? bq2 : bq, inp ? bk2 : bk, inp ? bv2 : bv };

    if (tid < 128) {
        mu_s[tid] = g_mean[inp * NPIX + p0 + tid];
        rs_s[tid] = g_rstd[inp * NPIX + p0 + tid];
    }
    __syncthreads();

    const float* Xb = X + (size_t)b * CHWN + pix0;
#pragma unroll 2
    for (int ch2 = 0; ch2 < 2; ch2++) {
        uint2* Bt = ch2 ? B2b : B2a;
        int c0 = ch2 * 64;
#pragma unroll
        for (int it = 0; it < 16; it++) {
            int idx = it * 512 + tid;
            int kc = idx >> 7, p = idx & 127;
            float v = Xb[(size_t)(c0 + kc) * HWN + p];
            Bt[kc * PKM + p] = split2((v - mu_s[p]) * rs_s[p] * __ldg(&gamma[c0 + kc]));
        }
    }

    int m0 = (wid & 3) * 32, n0w = (wid >> 2) * 32;
    int r = lane >> 2, q = lane & 3;

    for (int i = 0; i < 3; i++) {
        const uint2* Wsrc = g_w2 + (size_t)(inp * 3 + i) * CN * CN;
        float c4[2][4][4];
        ZERO_C44(c4);
#pragma unroll 2
        for (int ch = 0; ch < 2; ch++) {
            __syncthreads();
#pragma unroll
            for (int it = 0; it < 8; it++) {
                int idx = (it * 512 + tid) * 2;
                int o = idx >> 6, kc = idx & 63;
                *(uint4*)(A2 + o * PMK + kc) =
                    *(const uint4*)(Wsrc + o * CN + ch * 64 + kc);
            }
            __syncthreads();
            gemm64<false, true>(A2, ch ? B2b : B2a, c4, m0, n0w, r, q);
        }
        const float* bias = Bs3[i];
        float* Ob = g_pre + ((size_t)(inp * 3 + i) * BB + b) * CHWN;
#pragma unroll
        for (int mi = 0; mi < 2; mi++) {
            int o0 = m0 + mi * 16 + r;
            float bo0 = __ldg(&bias[o0]), bo1 = __ldg(&bias[o0 + 8]);
#pragma unroll
            for (int ni = 0; ni < 4; ni++) {
                int col = pix0 + n0w + ni * 8 + 2 * q;
                *(float2*)&Ob[(size_t)o0 * HWN + col] =
                    make_float2(c4[mi][ni][0] + bo0, c4[mi][ni][1] + bo0);
                *(float2*)&Ob[(size_t)(o0 + 8) * HWN + col] =
                    make_float2(c4[mi][ni][2] + bo1, c4[mi][ni][3] + bo1);
            }
        }
    }
}

// ---------------- kernel 2: depthwise 3x3 (4 outputs/thread) ----------------
__global__ __launch_bounds__(256) void k_dw(
    const float* d0, const float* d1, const float* d2,
    const float* d3, const float* d4, const float* d5,
    const float* e0, const float* e1, const float* e2,
    const float* e3, const float* e4, const float* e5) {
    int br = blockIdx.z, b = blockIdx.y;
    int base = blockIdx.x * 1024 + threadIdx.x * 4;    // grid.x = CHWN/1024
    int c = base >> 14, pix = base & 16383, h = pix >> 7, w0 = pix & 127;
    const float* Wd6[6] = {d0, d1, d2, d3, d4, d5};
    const float* Bd6[6] = {e0, e1, e2, e3, e4, e5};
    const float* Wd = Wd6[br] + c * 9;
    const float* In = g_pre + (size_t)br * BCHWN + (size_t)b * CHWN + (size_t)c * HWN;
    float bias = __ldg(&Bd6[br][c]);
    float a0 = bias, a1 = bias, a2 = bias, a3 = bias;
#pragma unroll
    for (int dy = -1; dy <= 1; dy++) {
        int hh = h + dy;
        if ((unsigned)hh < (unsigned)HN) {
            const float* row = In + hh * WN;
            float4 v = *(const float4*)(row + w0);
            float xl = (w0 > 0)   ? row[w0 - 1] : 0.f;
            float xr = (w0 < 124) ? row[w0 + 4] : 0.f;
            float k0 = __ldg(&Wd[(dy + 1) * 3 + 0]);
            float k1 = __ldg(&Wd[(dy + 1) * 3 + 1]);
            float k2 = __ldg(&Wd[(dy + 1) * 3 + 2]);
            a0 += k0 * xl  + k1 * v.x + k2 * v.y;
            a1 += k0 * v.x + k1 * v.y + k2 * v.z;
            a2 += k0 * v.y + k1 * v.z + k2 * v.w;
            a3 += k0 * v.z + k1 * v.w + k2 * xr;
        }
    }
    if (br == 2 || br == 5) {                          // V branches -> bf16 packed
        int vs = (br == 5);
        uint32_t* Op = g_postv + ((size_t)vs * BB + b) * CHWN + (base & (CHWN - 1));
        *(uint4*)Op = make_uint4(bsplit(a0), bsplit(a1), bsplit(a2), bsplit(a3));
    } else {                                           // Q/K -> tf32 pairs
        int qs = (br < 2) ? br : br - 1;               // 0,1,3,4 -> 0,1,2,3
        uint2* Op = g_post2 + ((size_t)qs * BB + b) * CHWN + (base & (CHWN - 1));
        uint2 s0 = split2(a0), s1 = split2(a1), s2 = split2(a2), s3 = split2(a3);
        *(uint4*)(Op)     = make_uint4(s0.x, s0.y, s1.x, s1.y);
        *(uint4*)(Op + 2) = make_uint4(s2.x, s2.y, s3.x, s3.y);
    }
}

// ---------------- kernel 3: S partials (tf32x3, 256 thr, K-chunk 32) --------
// C[c][d] = sum_n Q[n][c] K[n][d]
__global__ __launch_bounds__(256, 2) void k_qk() {
    extern __shared__ char smraw[];
    uint2* A2 = (uint2*)smraw;
    uint2* B2 = (uint2*)(smraw + QK_TILE);
    int tid = threadIdx.x, wid = tid >> 5, lane = tid & 31;
    int s = blockIdx.x, b = blockIdx.y, att = blockIdx.z;
    int qslot = (att == 0) ? 0 : 2;
    int kslot = (att == 0) ? 3 : 1;
    const uint2* Q2 = g_post2 + (size_t)qslot * BCHWN + (size_t)b * CHWN;
    const uint2* K2 = g_post2 + (size_t)kslot * BCHWN + (size_t)b * CHWN;

    int m0 = (wid & 3) * 32, n0w = (wid >> 2) * 64;
    int r = lane >> 2, q = lane & 3;
    float c4[2][8][4];
    ZERO_C48(c4);

    for (int ch = 0; ch < 32; ch++) {
        size_t nb = ((size_t)s * 1024 + ch * 32) * CN;
        __syncthreads();
#pragma unroll
        for (int it = 0; it < 8; it++) {               // FIX: full 32-row coverage
            int idx = it * 256 + tid;                  // [0, 2048)
            int n = idx >> 6, c2 = (idx & 63) * 2;     // n in [0,32)
            *(uint4*)(A2 + n * PKM + c2) = *(const uint4*)(Q2 + nb + (size_t)n * CN + c2);
            *(uint4*)(B2 + n * PKM + c2) = *(const uint4*)(K2 + nb + (size_t)n * CN + c2);
        }
        __syncthreads();
        gemm32t(A2, B2, c4, m0, n0w, r, q);
    }

    float* Sp = g_Spart + ((size_t)(att * NSPLIT + s) * BB + b) * (CN * CN);
#pragma unroll
    for (int mi = 0; mi < 2; mi++) {
        int c0 = m0 + mi * 16 + r;
#pragma unroll
        for (int ni = 0; ni < 8; ni++) {
            int col = n0w + ni * 8 + 2 * q;
            *(float2*)&Sp[c0 * CN + col] = make_float2(c4[mi][ni][0], c4[mi][ni][1]);
            *(float2*)&Sp[(c0 + 8) * CN + col] = make_float2(c4[mi][ni][2], c4[mi][ni][3]);
        }
    }
}

// ---------------- kernel 4: reduce partials + softmax -> bf16 packed --------
__global__ __launch_bounds__(256) void k_softmax() {
    int row  = blockIdx.x * 8 + (threadIdx.x >> 5);
    int lane = threadIdx.x & 31;
    int att = row >> 10, rb = row & 1023, b = rb >> 7, c = rb & 127;
    float v[4];
#pragma unroll
    for (int q = 0; q < 4; q++) {
        int d = lane + 32 * q;
        float s = 0.f;
        for (int sp = 0; sp < NSPLIT; sp++)
            s += g_Spart[((size_t)(att * NSPLIT + sp) * BB + b) * (CN * CN) + c * CN + d];
        v[q] = s;
    }
    float mx = fmaxf(fmaxf(v[0], v[1]), fmaxf(v[2], v[3]));
#pragma unroll
    for (int o = 16; o > 0; o >>= 1) mx = fmaxf(mx, __shfl_xor_sync(0xffffffffu, mx, o));
    float e[4], sum = 0.f;
#pragma unroll
    for (int q = 0; q < 4; q++) { e[q] = __expf(v[q] - mx); sum += e[q]; }
#pragma unroll
    for (int o = 16; o > 0; o >>= 1) sum += __shfl_xor_sync(0xffffffffu, sum, o);
    float inv = 1.f / sum;
#pragma unroll
    for (int q = 0; q < 4; q++)
        g_S2[(size_t)(att * BB + b) * (CN * CN) + c * CN + lane + 32 * q] =
            bsplit(e[q] * inv);
}

// ---------------- kernel 5: A@V (bf16x3) ----------------
// C[npix][c] = sum_d V[d][n0+npix] * S[c][d]
__global__ __launch_bounds__(256, 2) void k_av() {
    extern __shared__ char smraw[];
    uint2* A2 = (uint2*)smraw;
    uint2* B2 = (uint2*)(smraw + BF_TILE);
    int tid = threadIdx.x, wid = tid >> 5, lane = tid & 31;
    int nt = blockIdx.x, b = blockIdx.y, att = blockIdx.z;
    int vslot = (att == 0) ? 1 : 0;
    const uint32_t* Sp = g_S2 + (size_t)(att * BB + b) * (CN * CN);
    const uint32_t* Vp = g_postv + ((size_t)vslot * BB + b) * CHWN;
    int n0 = nt * 128;

    int m0 = (wid & 3) * 32, n0w = (wid >> 2) * 64;
    int r = lane >> 2, q = lane & 3;
    float c4[2][8][4];
    ZERO_C48(c4);

#pragma unroll 2
    for (int chk = 0; chk < 2; chk++) {
        int d0 = chk * 64;
        __syncthreads();
#pragma unroll
        for (int it = 0; it < 4; it++) {               // A = V [d2][p]
            int idx = it * 256 + tid;
            int d2 = idx >> 5, p4 = (idx & 31) * 4;
            uint4 v0 = *(const uint4*)(Vp + (size_t)(d0 + 2 * d2) * HWN + n0 + p4);
            uint4 v1 = *(const uint4*)(Vp + (size_t)(d0 + 2 * d2 + 1) * HWN + n0 + p4);
            uint2* dst = A2 + d2 * PB + p4;
            dst[0] = make_uint2(__byte_perm(v0.x, v1.x, 0x5410), __byte_perm(v0.x, v1.x, 0x7632));
            dst[1] = make_uint2(__byte_perm(v0.y, v1.y, 0x5410), __byte_perm(v0.y, v1.y, 0x7632));
            dst[2] = make_uint2(__byte_perm(v0.z, v1.z, 0x5410), __byte_perm(v0.z, v1.z, 0x7632));
            dst[3] = make_uint2(__byte_perm(v0.w, v1.w, 0x5410), __byte_perm(v0.w, v1.w, 0x7632));
        }
#pragma unroll
        for (int it = 0; it < 8; it++) {               // B = S [d2][c]
            int idx = it * 256 + tid;
            int d2g = idx & 15, c = idx >> 4;
            uint4 sv = *(const uint4*)(Sp + c * CN + d0 + 4 * d2g);
            B2[(2 * d2g) * PB + c] =
                make_uint2(__byte_perm(sv.x, sv.y, 0x5410), __byte_perm(sv.x, sv.y, 0x7632));
            B2[(2 * d2g + 1) * PB + c] =
                make_uint2(__byte_perm(sv.z, sv.w, 0x5410), __byte_perm(sv.z, sv.w, 0x7632));
        }
        __syncthreads();
        gemm_bf(A2, B2, c4, m0, n0w, r, q);
    }

    uint32_t* Out = g_A + (size_t)att * BCHWN + (size_t)b * CHWN;
#pragma unroll
    for (int mi = 0; mi < 2; mi++) {
        int rr = m0 + mi * 16 + r;                     // n index
#pragma unroll
        for (int ni = 0; ni < 8; ni++) {
            int cc = n0w + ni * 8 + 2 * q;             // c index
            Out[(size_t)cc * HWN + n0 + rr]           = bsplit(c4[mi][ni][0]);
            Out[(size_t)(cc + 1) * HWN + n0 + rr]     = bsplit(c4[mi][ni][1]);
            Out[(size_t)cc * HWN + n0 + rr + 8]       = bsplit(c4[mi][ni][2]);
            Out[(size_t)(cc + 1) * HWN + n0 + rr + 8] = bsplit(c4[mi][ni][3]);
        }
    }
}

// ---------------- kernel 6: final linear (bf16x3) ----------------
// C[pix][co] = sum_t flat[pix][t] lw[co][t]
__global__ __launch_bounds__(256, 2) void k_final(const float* __restrict__ lb) {
    extern __shared__ char smraw[];
    uint2* A2 = (uint2*)smraw;
    uint2* B2 = (uint2*)(smraw + BF_TILE);
    int tid = threadIdx.x, wid = tid >> 5, lane = tid & 31;
    int nt = blockIdx.x, b = blockIdx.y;
    int n0 = nt * 128;

    int m0 = (wid & 3) * 32, n0w = (wid >> 2) * 64;
    int r = lane >> 2, q = lane & 3;
    float c4[2][8][4];
    ZERO_C48(c4);

    for (int chk = 0; chk < 4; chk++) {
        int part = chk >> 1, tloc = (chk & 1) * 64;
        const uint32_t* Ap = g_A + ((size_t)part * BB + b) * CHWN + (size_t)n0 * CN;
        __syncthreads();
#pragma unroll
        for (int it = 0; it < 8; it++) {               // A = flat [t2][pix]
            int idx = it * 256 + tid;
            int tg = idx & 15, p = idx >> 4;
            uint4 av = *(const uint4*)(Ap + p * CN + tloc + 4 * tg);
            A2[(2 * tg) * PB + p] =
                make_uint2(__byte_perm(av.x, av.y, 0x5410), __byte_perm(av.x, av.y, 0x7632));
            A2[(2 * tg + 1) * PB + p] =
                make_uint2(__byte_perm(av.z, av.w, 0x5410), __byte_perm(av.z, av.w, 0x7632));
        }
#pragma unroll
        for (int it = 0; it < 8; it++) {               // B = lw [t2][co]
            int idx = it * 256 + tid;
            int tg = idx & 15, co = idx >> 4;
            uint4 lv = *(const uint4*)(g_lw2b + co * 256 + part * 128 + tloc + 4 * tg);
            B2[(2 * tg) * PB + co] =
                make_uint2(__byte_perm(lv.x, lv.y, 0x5410), __byte_perm(lv.x, lv.y, 0x7632));
            B2[(2 * tg + 1) * PB + co] =
                make_uint2(__byte_perm(lv.z, lv.w, 0x5410), __byte_perm(lv.z, lv.w, 0x7632));
        }
        __syncthreads();
        gemm_bf(A2, B2, c4, m0, n0w, r, q);
    }

    float* Ob = g_lin + (size_t)b * CHWN;
#pragma unroll
    for (int mi = 0; mi < 2; mi++) {
        int p0r = n0 + m0 + mi * 16 + r;
#pragma unroll
        for (int ni = 0; ni < 8; ni++) {
            int col = n0w + ni * 8 + 2 * q;
            float b0 = __ldg(&lb[col]), b1 = __ldg(&lb[col + 1]);
            *(float2*)&Ob[(size_t)p0r * CN + col] =
                make_float2(c4[mi][ni][0] + b0, c4[mi][ni][1] + b1);
            *(float2*)&Ob[(size_t)(p0r + 8) * CN + col] =
                make_float2(c4[mi][ni][2] + b0, c4[mi][ni][3] + b1);
        }
    }
}

// ---------------- kernel 7: tail transpose + residual ----------------
__global__ __launch_bounds__(256) void k_tail(const float* __restrict__ Fi,
                                              const float* __restrict__ Fw,
                                              float* __restrict__ out) {
    __shared__ float tile[32][33];
    int b  = blockIdx.z;
    int r0 = blockIdx.x * 32;
    int c0 = blockIdx.y * 32;
    const float* In = g_lin + (size_t)b * CHWN;
    int tx = threadIdx.x & 31, ty = threadIdx.x >> 5;
#pragma unroll
    for (int s2 = 0; s2 < 4; s2++) {
        int cc = c0 + ty + 8 * s2;
        tile[ty + 8 * s2][tx] = In[(size_t)cc * HWN + r0 + tx];
    }
    __syncthreads();
    size_t base = (size_t)b * CHWN;
#pragma unroll
    for (int s2 = 0; s2 < 4; s2++) {
        int r = r0 + ty + 8 * s2;
        size_t idx = base + (size_t)r * CN + c0 + tx;
        out[idx] = tile[tx][ty + 8 * s2] + Fi[idx] + Fw[idx];
    }
}

// ---------------- launch ----------------
extern "C" void kernel_launch(void* const* d_in, const int* in_sizes, int n_in,
                              void* d_out, int out_size) {
    const float* Fi = (const float*)d_in[0];
    const float* Fw = (const float*)d_in[1];
    const float* g1 = (const float*)d_in[2];
    const float* g2 = (const float*)d_in[3];

    const float *qw1, *kw1, *vw1, *qw2, *kw2, *vw2;
    const float *qb1, *kb1, *vb1, *qb2, *kb2, *vb2;
    const float *qdw1, *kdw1, *vdw1, *qdw2, *kdw2, *vdw2;
    const float *qdb1, *kdb1, *vdb1, *qdb2, *kdb2, *vdb2;
    const float *lw, *lb;

    if (in_sizes[5] == CN) {
        qw1 = (const float*)d_in[4];  qb1 = (const float*)d_in[5];
        kw1 = (const float*)d_in[6];  kb1 = (const float*)d_in[7];
        vw1 = (const float*)d_in[8];  vb1 = (const float*)d_in[9];
        qw2 = (const float*)d_in[10]; qb2 = (const float*)d_in[11];
        kw2 = (const float*)d_in[12]; kb2 = (const float*)d_in[13];
        vw2 = (const float*)d_in[14]; vb2 = (const float*)d_in[15];
        qdw1 = (const float*)d_in[16]; qdb1 = (const float*)d_in[17];
        kdw1 = (const float*)d_in[18]; kdb1 = (const float*)d_in[19];
        vdw1 = (const float*)d_in[20]; vdb1 = (const float*)d_in[21];
        qdw2 = (const float*)d_in[22]; qdb2 = (const float*)d_in[23];
        kdw2 = (const float*)d_in[24]; kdb2 = (const float*)d_in[25];
        vdw2 = (const float*)d_in[26]; vdb2 = (const float*)d_in[27];
    } else {
        qw1 = (const float*)d_in[4];  kw1 = (const float*)d_in[5];
        vw1 = (const float*)d_in[6];  qw2 = (const float*)d_in[7];
        kw2 = (const float*)d_in[8];  vw2 = (const float*)d_in[9];
        qb1 = (const float*)d_in[10]; kb1 = (const float*)d_in[11];
        vb1 = (const float*)d_in[12]; qb2 = (const float*)d_in[13];
        kb2 = (const float*)d_in[14]; vb2 = (const float*)d_in[15];
        qdw1 = (const float*)d_in[16]; kdw1 = (const float*)d_in[17];
        vdw1 = (const float*)d_in[18]; qdw2 = (const float*)d_in[19];
        kdw2 = (const float*)d_in[20]; vdw2 = (const float*)d_in[21];
        qdb1 = (const float*)d_in[22]; kdb1 = (const float*)d_in[23];
        vdb1 = (const float*)d_in[24]; qdb2 = (const float*)d_in[25];
        kdb2 = (const float*)d_in[26]; vdb2 = (const float*)d_in[27];
    }
    lw = (const float*)d_in[28];
    lb = (const float*)d_in[29];
    float* out = (float*)d_out;

    cudaFuncSetAttribute(k_ln_c11, cudaFuncAttributeMaxDynamicSharedMemorySize, SMEM_LN);
    cudaFuncSetAttribute(k_qk,     cudaFuncAttributeMaxDynamicSharedMemorySize, SMEM_QK);
    cudaFuncSetAttribute(k_av,     cudaFuncAttributeMaxDynamicSharedMemorySize, SMEM_BF);
    cudaFuncSetAttribute(k_final,  cudaFuncAttributeMaxDynamicSharedMemorySize, SMEM_BF);

    k_stats  <<<dim3(NPIX / 256, 2), 256>>>(Fi, Fw);
    k_splitw <<<dim3(512), 256>>>(qw1, kw1, vw1, qw2, kw2, vw2, lw);
    k_ln_c11 <<<dim3(NPIX / 128, 2), 512, SMEM_LN>>>(Fi, Fw, g1, g2,
                                                     qb1, kb1, vb1, qb2, kb2, vb2);
    k_dw     <<<dim3(CHWN / 1024, BB, 6), 256>>>(qdw1, kdw1, vdw1, qdw2, kdw2, vdw2,
                                                 qdb1, kdb1, vdb1, qdb2, kdb2, vdb2);
    k_qk     <<<dim3(NSPLIT, BB, 2), 256, SMEM_QK>>>();
    k_softmax<<<dim3(256), 256>>>();
    k_av     <<<dim3(HWN / 128, BB, 2), 256, SMEM_BF>>>();
    k_final  <<<dim3(HWN / 128, BB), 256, SMEM_BF>>>(lb);
    k_tail   <<<dim3(HWN / 32, CN / 32, BB), 256>>>(Fi, Fw, out);
}

// round 14
// speedup vs baseline: 2.3818x; 1.0845x over previous
#include <cuda_runtime.h>
#include <cuda_bf16.h>
#include <cstdint>

// ---------------- problem constants ----------------
#define BB    8
#define CN    128
#define HN    128
#define WN    128
#define HWN   16384
#define CHWN  (CN*HWN)                 // 2,097,152
#define BCHWN (BB*CHWN)                // 16,777,216
#define NPIX  (BB*HWN)                 // 131,072
#define NSPLIT 16

// tf32 smem layouts (uint2 {tf32_hi, tf32_lo}) for ln:
#define PKM 130
#define PMK 66
#define TILE_BYTES 67584
#define SMEM_LN (3*TILE_BYTES + 8192)
// bf16 pair layout: [k2][m] of uint2 {hi_bf16x2, lo_bf16x2}, pitch 131
#define PB 131
#define BF_TILE (32*PB*8)              // 33568
#define SMEM_BF (2*BF_TILE + 512)

// ---------------- device scratch ----------------
__device__ float g_pre [6ull*BCHWN];                        // conv1x1 out (fp32)
__device__ __align__(16) uint32_t g_postall[6ull*BCHWN];    // dw out, bf16 packed
__device__ float g_Spart[2ull*NSPLIT*BB*CN*CN];
__device__ __align__(16) uint32_t g_S2[2ull*BB*CN*CN];      // softmax (bf16 packed)
__device__ __align__(16) uint32_t g_A [2ull*BCHWN];         // attn out (bf16 packed)
__device__ float g_lin [1ull*BCHWN];
__device__ __align__(16) uint2    g_w2 [6*CN*CN];           // 1x1 W (tf32 pairs)
__device__ __align__(16) uint32_t g_lw2b[2*CN*CN];          // lw (bf16 packed)

// ---------------- splits ----------------
__device__ __forceinline__ uint2 split2(float x) {          // tf32 hi/lo
    uint32_t h;
    asm("cvt.rna.tf32.f32 %0, %1;" : "=r"(h) : "f"(x));
    float l = x - __uint_as_float(h);
    uint32_t lo;
    asm("cvt.rna.tf32.f32 %0, %1;" : "=r"(lo) : "f"(l));
    return make_uint2(h, lo);
}
__device__ __forceinline__ uint32_t bsplit(float x) {       // bf16 hi/lo packed
    __nv_bfloat16 h = __float2bfloat16(x);
    float l = x - __bfloat162float(h);
    __nv_bfloat16 lo = __float2bfloat16(l);
    return ((uint32_t)__bfloat16_as_ushort(lo) << 16) |
           (uint32_t)__bfloat16_as_ushort(h);
}

// ---------------- mma wrappers ----------------
__device__ __forceinline__ void mma8(float c[4], const uint32_t a[4],
                                     uint32_t b0, uint32_t b1) {
    asm volatile(
        "mma.sync.aligned.m16n8k8.row.col.f32.tf32.tf32.f32 "
        "{%0,%1,%2,%3},{%4,%5,%6,%7},{%8,%9},{%0,%1,%2,%3};"
        : "+f"(c[0]), "+f"(c[1]), "+f"(c[2]), "+f"(c[3])
        : "r"(a[0]), "r"(a[1]), "r"(a[2]), "r"(a[3]), "r"(b0), "r"(b1));
}
__device__ __forceinline__ void mmabf(float c[4], const uint32_t a[4],
                                      uint32_t b0, uint32_t b1) {
    asm volatile(
        "mma.sync.aligned.m16n8k16.row.col.f32.bf16.bf16.f32 "
        "{%0,%1,%2,%3},{%4,%5,%6,%7},{%8,%9},{%0,%1,%2,%3};"
        : "+f"(c[0]), "+f"(c[1]), "+f"(c[2]), "+f"(c[3])
        : "r"(a[0]), "r"(a[1]), "r"(a[2]), "r"(a[3]), "r"(b0), "r"(b1));
}

#define ZERO_C44(c4) {                                 \
    _Pragma("unroll") for (int mi = 0; mi < 2; mi++)   \
    _Pragma("unroll") for (int ni = 0; ni < 4; ni++)   \
    _Pragma("unroll") for (int t = 0; t < 4; t++) (c4)[mi][ni][t] = 0.f; }
#define ZERO_C48(c4) {                                 \
    _Pragma("unroll") for (int mi = 0; mi < 2; mi++)   \
    _Pragma("unroll") for (int ni = 0; ni < 8; ni++)   \
    _Pragma("unroll") for (int t = 0; t < 4; t++) (c4)[mi][ni][t] = 0.f; }

// bf16 pair KM/KM, K=64 chunk (32 k2-rows), warp tile 32x64
__device__ __forceinline__ void gemm_bf(const uint2* __restrict__ A2,
                                        const uint2* __restrict__ B2,
                                        float c4[2][8][4],
                                        int m0, int n0w, int r, int q) {
#pragma unroll
    for (int ks = 0; ks < 4; ks++) {
        int k2a = ks * 8 + q, k2b = ks * 8 + q + 4;
        uint32_t ah[2][4], al[2][4];
#pragma unroll
        for (int mi = 0; mi < 2; mi++) {
            int m = m0 + mi * 16 + r;
            uint2 u0 = A2[k2a * PB + m];
            uint2 u1 = A2[k2a * PB + m + 8];
            uint2 u2 = A2[k2b * PB + m];
            uint2 u3 = A2[k2b * PB + m + 8];
            ah[mi][0] = u0.x; ah[mi][1] = u1.x; ah[mi][2] = u2.x; ah[mi][3] = u3.x;
            al[mi][0] = u0.y; al[mi][1] = u1.y; al[mi][2] = u2.y; al[mi][3] = u3.y;
        }
#pragma unroll
        for (int ni = 0; ni < 8; ni++) {
            int col = n0w + ni * 8 + r;
            uint2 v0 = B2[k2a * PB + col];
            uint2 v1 = B2[k2b * PB + col];
#pragma unroll
            for (int mi = 0; mi < 2; mi++) {
                mmabf(c4[mi][ni], ah[mi], v0.x, v1.x);
                mmabf(c4[mi][ni], al[mi], v0.x, v1.x);
                mmabf(c4[mi][ni], ah[mi], v0.y, v1.y);
            }
        }
    }
}

// tf32 gemm for ln (A=MK pitch 66, B=KM pitch 130, K=64, 16 warps 32x32)
__device__ __forceinline__ void gemm64(const uint2* __restrict__ A2,
                                       const uint2* __restrict__ B2,
                                       float c4[2][4][4],
                                       int m0, int n0w, int r, int q) {
#pragma unroll
    for (int ks = 0; ks < 8; ks++) {
        int k0 = ks * 8;
        uint32_t ah[2][4], al[2][4];
#pragma unroll
        for (int mi = 0; mi < 2; mi++) {
            int m = m0 + mi * 16 + r;
            uint2 p0 = A2[m * PMK + k0 + q];
            uint2 p1 = A2[(m + 8) * PMK + k0 + q];
            uint2 p2 = A2[m * PMK + k0 + q + 4];
            uint2 p3 = A2[(m + 8) * PMK + k0 + q + 4];
            ah[mi][0] = p0.x; ah[mi][1] = p1.x; ah[mi][2] = p2.x; ah[mi][3] = p3.x;
            al[mi][0] = p0.y; al[mi][1] = p1.y; al[mi][2] = p2.y; al[mi][3] = p3.y;
        }
#pragma unroll
        for (int ni = 0; ni < 4; ni++) {
            int col = n0w + ni * 8 + r;
            uint2 v0 = B2[(k0 + q) * PKM + col];
            uint2 v1 = B2[(k0 + q + 4) * PKM + col];
#pragma unroll
            for (int mi = 0; mi < 2; mi++) {
                mma8(c4[mi][ni], ah[mi], v0.x, v1.x);
                mma8(c4[mi][ni], al[mi], v0.x, v1.x);
                mma8(c4[mi][ni], ah[mi], v0.y, v1.y);
            }
        }
    }
}

// ---------------- kernel 0b: pre-split weights ----------------
__global__ __launch_bounds__(256) void k_splitw(
    const float* w0, const float* w1, const float* w2,
    const float* w3, const float* w4, const float* w5,
    const float* lw) {
    int i = blockIdx.x * 256 + threadIdx.x;
    if (i < 6 * CN * CN) {
        const float* srcs[6] = {w0, w1, w2, w3, w4, w5};
        g_w2[i] = split2(srcs[i >> 14][i & 16383]);
    } else {
        int j = i - 6 * CN * CN;
        g_lw2b[j] = bsplit(lw[j]);
    }
}

// ---------------- kernel 1: fused stats + LN + 3x(1x1 conv) (tf32x3) -------
__global__ __launch_bounds__(512, 1) void k_ln_c11(
    const float* __restrict__ Fi, const float* __restrict__ Fw,
    const float* __restrict__ g1, const float* __restrict__ g2,
    const float* bq, const float* bk, const float* bv,
    const float* bq2, const float* bk2, const float* bv2) {
    extern __shared__ char smraw[];
    float* Xraw = (float*)smraw;                       // [128][129] raw X
    uint2* A2  = (uint2*)smraw;                        // later: W tiles
    uint2* B2a = (uint2*)(smraw + TILE_BYTES);
    uint2* B2b = (uint2*)(smraw + 2 * TILE_BYTES);
    float* mu_s = (float*)(smraw + 3 * TILE_BYTES);
    float* rs_s = mu_s + 128;
    float* gm_s = rs_s + 128;
    float* redS = gm_s + 128;                          // [4][128]
    float* redQ = redS + 512;                          // [4][128]

    int tid = threadIdx.x, wid = tid >> 5, lane = tid & 31;
    int inp = blockIdx.y;
    int p0 = blockIdx.x * 128;
    int b = p0 >> 14, pix0 = p0 & (HWN - 1);
    const float* X = inp ? Fw : Fi;
    const float* gamma = inp ? g2 : g1;
    const float* Bs3[3] = { inp ? bq2 : bq, inp ? bk2 : bk, inp ? bv2 : bv };

    if (tid < 128) gm_s[tid] = gamma[tid];

    // phase A: raw X tile to smem
    const float* Xb = X + (size_t)b * CHWN + pix0;
#pragma unroll 8
    for (int it = 0; it < 32; it++) {
        int idx = it * 512 + tid;
        Xraw[(idx >> 7) * 129 + (idx & 127)] = Xb[(size_t)(idx >> 7) * HWN + (idx & 127)];
    }
    __syncthreads();

    // phase B: per-pixel LN stats
    {
        int p = tid & 127, g = tid >> 7;
        float s = 0.f, ss = 0.f;
#pragma unroll 8
        for (int kc = g * 32; kc < g * 32 + 32; kc++) {
            float v = Xraw[kc * 129 + p];
            s += v; ss += v * v;
        }
        redS[g * 128 + p] = s;
        redQ[g * 128 + p] = ss;
    }
    __syncthreads();
    if (tid < 128) {
        float s  = redS[tid] + redS[128 + tid] + redS[256 + tid] + redS[384 + tid];
        float ss = redQ[tid] + redQ[128 + tid] + redQ[256 + tid] + redQ[384 + tid];
        float m = s * (1.f / CN);
        mu_s[tid] = m;
        rs_s[tid] = rsqrtf(ss * (1.f / CN) - m * m + 1e-5f);
    }
    __syncthreads();

    // phase C: normalize + tf32 split into B tiles
#pragma unroll 8
    for (int it = 0; it < 32; it++) {
        int idx = it * 512 + tid;
        int kc = idx >> 7, p = idx & 127;
        float v = Xraw[kc * 129 + p];
        uint2 sp = split2((v - mu_s[p]) * rs_s[p] * gm_s[kc]);
        if (kc < 64) B2a[kc * PKM + p] = sp;
        else         B2b[(kc - 64) * PKM + p] = sp;
    }

    int m0 = (wid & 3) * 32, n0w = (wid >> 2) * 32;
    int r = lane >> 2, q = lane & 3;

    for (int i = 0; i < 3; i++) {
        const uint2* Wsrc = g_w2 + (size_t)(inp * 3 + i) * CN * CN;
        float c4[2][4][4];
        ZERO_C44(c4);
#pragma unroll 2
        for (int ch = 0; ch < 2; ch++) {
            __syncthreads();
#pragma unroll
            for (int it = 0; it < 8; it++) {
                int idx = (it * 512 + tid) * 2;
                int o = idx >> 6, kc = idx & 63;
                *(uint4*)(A2 + o * PMK + kc) =
                    *(const uint4*)(Wsrc + o * CN + ch * 64 + kc);
            }
            __syncthreads();
            gemm64(A2, ch ? B2b : B2a, c4, m0, n0w, r, q);
        }
        const float* bias = Bs3[i];
        float* Ob = g_pre + ((size_t)(inp * 3 + i) * BB + b) * CHWN;
#pragma unroll
        for (int mi = 0; mi < 2; mi++) {
            int o0 = m0 + mi * 16 + r;
            float bo0 = __ldg(&bias[o0]), bo1 = __ldg(&bias[o0 + 8]);
#pragma unroll
            for (int ni = 0; ni < 4; ni++) {
                int col = pix0 + n0w + ni * 8 + 2 * q;
                *(float2*)&Ob[(size_t)o0 * HWN + col] =
                    make_float2(c4[mi][ni][0] + bo0, c4[mi][ni][1] + bo0);
                *(float2*)&Ob[(size_t)(o0 + 8) * HWN + col] =
                    make_float2(c4[mi][ni][2] + bo1, c4[mi][ni][3] + bo1);
            }
        }
    }
}

// ---------------- kernel 2: depthwise 3x3, smem-tiled, bf16 out ------------
__global__ __launch_bounds__(256) void k_dw(
    const float* d0, const float* d1, const float* d2,
    const float* d3, const float* d4, const float* d5,
    const float* e0, const float* e1, const float* e2,
    const float* e3, const float* e4, const float* e5) {
    __shared__ float s[10][128];
    int br = blockIdx.z, b = blockIdx.y;
    int c = blockIdx.x >> 4, rg = blockIdx.x & 15;
    int h0 = rg * 8;
    int tid = threadIdx.x;
    const float* Wd6[6] = {d0, d1, d2, d3, d4, d5};
    const float* Bd6[6] = {e0, e1, e2, e3, e4, e5};
    const float* In = g_pre + ((size_t)br * BB + b) * CHWN + (size_t)c * HWN;

#pragma unroll
    for (int i = tid; i < 1280; i += 256) {
        int row = i >> 7, col = i & 127;
        int gh = h0 - 1 + row;
        s[row][col] = ((unsigned)gh < 128u) ? In[(size_t)gh * WN + col] : 0.f;
    }
    __syncthreads();

    const float* Wd = Wd6[br] + c * 9;
    float kw[9];
#pragma unroll
    for (int i = 0; i < 9; i++) kw[i] = __ldg(&Wd[i]);
    float bias = __ldg(&Bd6[br][c]);

    int t4 = tid * 4, lr = t4 >> 7, w0 = t4 & 127;
    float a0 = bias, a1 = bias, a2 = bias, a3 = bias;
#pragma unroll
    for (int dy = 0; dy < 3; dy++) {
        const float* row = s[lr + dy];
        float4 v = *(const float4*)(row + w0);
        float xl = (w0 > 0)   ? row[w0 - 1] : 0.f;
        float xr = (w0 < 124) ? row[w0 + 4] : 0.f;
        float k0 = kw[dy * 3], k1 = kw[dy * 3 + 1], k2 = kw[dy * 3 + 2];
        a0 += k0 * xl  + k1 * v.x + k2 * v.y;
        a1 += k0 * v.x + k1 * v.y + k2 * v.z;
        a2 += k0 * v.y + k1 * v.z + k2 * v.w;
        a3 += k0 * v.z + k1 * v.w + k2 * xr;
    }
    uint32_t* Op = g_postall + ((size_t)br * BB + b) * CHWN + (size_t)c * HWN
                 + (size_t)h0 * WN + t4;
    *(uint4*)Op = make_uint4(bsplit(a0), bsplit(a1), bsplit(a2), bsplit(a3));
}

// ---------------- kernel 3: S partials (bf16x3) ----------------
// C[c][d] = sum_n Q[n][c] K[n][d]
__global__ __launch_bounds__(256, 2) void k_qk() {
    extern __shared__ char smraw[];
    uint2* A2 = (uint2*)smraw;
    uint2* B2 = (uint2*)(smraw + BF_TILE);
    int tid = threadIdx.x, wid = tid >> 5, lane = tid & 31;
    int s = blockIdx.x, b = blockIdx.y, att = blockIdx.z;
    int qbr = (att == 0) ? 0 : 3;                      // Qi / Qw
    int kbr = (att == 0) ? 4 : 1;                      // Kw / Ki
    const uint32_t* Qp = g_postall + ((size_t)qbr * BB + b) * CHWN;
    const uint32_t* Kp = g_postall + ((size_t)kbr * BB + b) * CHWN;

    int m0 = (wid & 3) * 32, n0w = (wid >> 2) * 64;
    int r = lane >> 2, q = lane & 3;
    float c4[2][8][4];
    ZERO_C48(c4);

    for (int ch = 0; ch < 16; ch++) {
        size_t nb = ((size_t)s * 1024 + ch * 64) * CN;
        __syncthreads();
#pragma unroll
        for (int it = 0; it < 4; it++) {
            int idx = it * 256 + tid;
            int n2 = idx >> 5, c4i = (idx & 31) * 4;
            uint4 q0 = *(const uint4*)(Qp + nb + (size_t)(2 * n2) * CN + c4i);
            uint4 q1 = *(const uint4*)(Qp + nb + (size_t)(2 * n2 + 1) * CN + c4i);
            uint2* da = A2 + n2 * PB + c4i;
            da[0] = make_uint2(__byte_perm(q0.x, q1.x, 0x5410), __byte_perm(q0.x, q1.x, 0x7632));
            da[1] = make_uint2(__byte_perm(q0.y, q1.y, 0x5410), __byte_perm(q0.y, q1.y, 0x7632));
            da[2] = make_uint2(__byte_perm(q0.z, q1.z, 0x5410), __byte_perm(q0.z, q1.z, 0x7632));
            da[3] = make_uint2(__byte_perm(q0.w, q1.w, 0x5410), __byte_perm(q0.w, q1.w, 0x7632));
            uint4 k0 = *(const uint4*)(Kp + nb + (size_t)(2 * n2) * CN + c4i);
            uint4 k1 = *(const uint4*)(Kp + nb + (size_t)(2 * n2 + 1) * CN + c4i);
            uint2* db = B2 + n2 * PB + c4i;
            db[0] = make_uint2(__byte_perm(k0.x, k1.x, 0x5410), __byte_perm(k0.x, k1.x, 0x7632));
            db[1] = make_uint2(__byte_perm(k0.y, k1.y, 0x5410), __byte_perm(k0.y, k1.y, 0x7632));
            db[2] = make_uint2(__byte_perm(k0.z, k1.z, 0x5410), __byte_perm(k0.z, k1.z, 0x7632));
            db[3] = make_uint2(__byte_perm(k0.w, k1.w, 0x5410), __byte_perm(k0.w, k1.w, 0x7632));
        }
        __syncthreads();
        gemm_bf(A2, B2, c4, m0, n0w, r, q);
    }

    float* Sp = g_Spart + ((size_t)(att * NSPLIT + s) * BB + b) * (CN * CN);
#pragma unroll
    for (int mi = 0; mi < 2; mi++) {
        int c0 = m0 + mi * 16 + r;
#pragma unroll
        for (int ni = 0; ni < 8; ni++) {
            int col = n0w + ni * 8 + 2 * q;
            *(float2*)&Sp[c0 * CN + col] = make_float2(c4[mi][ni][0], c4[mi][ni][1]);
            *(float2*)&Sp[(c0 + 8) * CN + col] = make_float2(c4[mi][ni][2], c4[mi][ni][3]);
        }
    }
}

// ---------------- kernel 4: reduce partials + softmax -> bf16 packed --------
__global__ __launch_bounds__(256) void k_softmax() {
    int row  = blockIdx.x * 8 + (threadIdx.x >> 5);
    int lane = threadIdx.x & 31;
    int att = row >> 10, rb = row & 1023, b = rb >> 7, c = rb & 127;
    float v[4];
#pragma unroll
    for (int q = 0; q < 4; q++) {
        int d = lane + 32 * q;
        float s = 0.f;
        for (int sp = 0; sp < NSPLIT; sp++)
            s += g_Spart[((size_t)(att * NSPLIT + sp) * BB + b) * (CN * CN) + c * CN + d];
        v[q] = s;
    }
    float mx = fmaxf(fmaxf(v[0], v[1]), fmaxf(v[2], v[3]));
#pragma unroll
    for (int o = 16; o > 0; o >>= 1) mx = fmaxf(mx, __shfl_xor_sync(0xffffffffu, mx, o));
    float e[4], sum = 0.f;
#pragma unroll
    for (int q = 0; q < 4; q++) { e[q] = __expf(v[q] - mx); sum += e[q]; }
#pragma unroll
    for (int o = 16; o > 0; o >>= 1) sum += __shfl_xor_sync(0xffffffffu, sum, o);
    float inv = 1.f / sum;
#pragma unroll
    for (int q = 0; q < 4; q++)
        g_S2[(size_t)(att * BB + b) * (CN * CN) + c * CN + lane + 32 * q] =
            bsplit(e[q] * inv);
}

// ---------------- kernel 5: A@V (bf16x3) ----------------
// C[npix][c] = sum_d V[d][n0+npix] * S[c][d]
__global__ __launch_bounds__(256, 2) void k_av() {
    extern __shared__ char smraw[];
    uint2* A2 = (uint2*)smraw;
    uint2* B2 = (uint2*)(smraw + BF_TILE);
    int tid = threadIdx.x, wid = tid >> 5, lane = tid & 31;
    int nt = blockIdx.x, b = blockIdx.y, att = blockIdx.z;
    int vbr = (att == 0) ? 5 : 2;                      // Vw / Vi
    const uint32_t* Sp = g_S2 + (size_t)(att * BB + b) * (CN * CN);
    const uint32_t* Vp = g_postall + ((size_t)vbr * BB + b) * CHWN;
    int n0 = nt * 128;

    int m0 = (wid & 3) * 32, n0w = (wid >> 2) * 64;
    int r = lane >> 2, q = lane & 3;
    float c4[2][8][4];
    ZERO_C48(c4);

#pragma unroll 2
    for (int chk = 0; chk < 2; chk++) {
        int d0 = chk * 64;
        __syncthreads();
#pragma unroll
        for (int it = 0; it < 4; it++) {               // A = V [d2][p]
            int idx = it * 256 + tid;
            int d2 = idx >> 5, p4 = (idx & 31) * 4;
            uint4 v0 = *(const uint4*)(Vp + (size_t)(d0 + 2 * d2) * HWN + n0 + p4);
            uint4 v1 = *(const uint4*)(Vp + (size_t)(d0 + 2 * d2 + 1) * HWN + n0 + p4);
            uint2* dst = A2 + d2 * PB + p4;
            dst[0] = make_uint2(__byte_perm(v0.x, v1.x, 0x5410), __byte_perm(v0.x, v1.x, 0x7632));
            dst[1] = make_uint2(__byte_perm(v0.y, v1.y, 0x5410), __byte_perm(v0.y, v1.y, 0x7632));
            dst[2] = make_uint2(__byte_perm(v0.z, v1.z, 0x5410), __byte_perm(v0.z, v1.z, 0x7632));
            dst[3] = make_uint2(__byte_perm(v0.w, v1.w, 0x5410), __byte_perm(v0.w, v1.w, 0x7632));
        }
#pragma unroll
        for (int it = 0; it < 8; it++) {               // B = S [d2][c]
            int idx = it * 256 + tid;
            int d2g = idx & 15, c = idx >> 4;
            uint4 sv = *(const uint4*)(Sp + c * CN + d0 + 4 * d2g);
            B2[(2 * d2g) * PB + c] =
                make_uint2(__byte_perm(sv.x, sv.y, 0x5410), __byte_perm(sv.x, sv.y, 0x7632));
            B2[(2 * d2g + 1) * PB + c] =
                make_uint2(__byte_perm(sv.z, sv.w, 0x5410), __byte_perm(sv.z, sv.w, 0x7632));
        }
        __syncthreads();
        gemm_bf(A2, B2, c4, m0, n0w, r, q);
    }

    uint32_t* Out = g_A + (size_t)att * BCHWN + (size_t)b * CHWN;
#pragma unroll
    for (int mi = 0; mi < 2; mi++) {
        int rr = m0 + mi * 16 + r;
#pragma unroll
        for (int ni = 0; ni < 8; ni++) {
            int cc = n0w + ni * 8 + 2 * q;
            Out[(size_t)cc * HWN + n0 + rr]           = bsplit(c4[mi][ni][0]);
            Out[(size_t)(cc + 1) * HWN + n0 + rr]     = bsplit(c4[mi][ni][1]);
            Out[(size_t)cc * HWN + n0 + rr + 8]       = bsplit(c4[mi][ni][2]);
            Out[(size_t)(cc + 1) * HWN + n0 + rr + 8] = bsplit(c4[mi][ni][3]);
        }
    }
}

// ---------------- kernel 6: final linear (bf16x3) ----------------
__global__ __launch_bounds__(256, 2) void k_final(const float* __restrict__ lb) {
    extern __shared__ char smraw[];
    uint2* A2 = (uint2*)smraw;
    uint2* B2 = (uint2*)(smraw + BF_TILE);
    int tid = threadIdx.x, wid = tid >> 5, lane = tid & 31;
    int nt = blockIdx.x, b = blockIdx.y;
    int n0 = nt * 128;

    int m0 = (wid & 3) * 32, n0w = (wid >> 2) * 64;
    int r = lane >> 2, q = lane & 3;
    float c4[2][8][4];
    ZERO_C48(c4);

    for (int chk = 0; chk < 4; chk++) {
        int part = chk >> 1, tloc = (chk & 1) * 64;
        const uint32_t* Ap = g_A + ((size_t)part * BB + b) * CHWN + (size_t)n0 * CN;
        __syncthreads();
#pragma unroll
        for (int it = 0; it < 8; it++) {               // A = flat [t2][pix]
            int idx = it * 256 + tid;
            int tg = idx & 15, p = idx >> 4;
            uint4 av = *(const uint4*)(Ap + p * CN + tloc + 4 * tg);
            A2[(2 * tg) * PB + p] =
                make_uint2(__byte_perm(av.x, av.y, 0x5410), __byte_perm(av.x, av.y, 0x7632));
            A2[(2 * tg + 1) * PB + p] =
                make_uint2(__byte_perm(av.z, av.w, 0x5410), __byte_perm(av.z, av.w, 0x7632));
        }
#pragma unroll
        for (int it = 0; it < 8; it++) {               // B = lw [t2][co]
            int idx = it * 256 + tid;
            int tg = idx & 15, co = idx >> 4;
            uint4 lv = *(const uint4*)(g_lw2b + co * 256 + part * 128 + tloc + 4 * tg);
            B2[(2 * tg) * PB + co] =
                make_uint2(__byte_perm(lv.x, lv.y, 0x5410), __byte_perm(lv.x, lv.y, 0x7632));
            B2[(2 * tg + 1) * PB + co] =
                make_uint2(__byte_perm(lv.z, lv.w, 0x5410), __byte_perm(lv.z, lv.w, 0x7632));
        }
        __syncthreads();
        gemm_bf(A2, B2, c4, m0, n0w, r, q);
    }

    float* Ob = g_lin + (size_t)b * CHWN;
#pragma unroll
    for (int mi = 0; mi < 2; mi++) {
        int p0r = n0 + m0 + mi * 16 + r;
#pragma unroll
        for (int ni = 0; ni < 8; ni++) {
            int col = n0w + ni * 8 + 2 * q;
            float b0 = __ldg(&lb[col]), b1 = __ldg(&lb[col + 1]);
            *(float2*)&Ob[(size_t)p0r * CN + col] =
                make_float2(c4[mi][ni][0] + b0, c4[mi][ni][1] + b1);
            *(float2*)&Ob[(size_t)(p0r + 8) * CN + col] =
                make_float2(c4[mi][ni][2] + b0, c4[mi][ni][3] + b1);
        }
    }
}

// ---------------- kernel 7: tail transpose + residual ----------------
__global__ __launch_bounds__(256) void k_tail(const float* __restrict__ Fi,
                                              const float* __restrict__ Fw,
                                              float* __restrict__ out) {
    __shared__ float tile[32][33];
    int b  = blockIdx.z;
    int r0 = blockIdx.x * 32;
    int c0 = blockIdx.y * 32;
    const float* In = g_lin + (size_t)b * CHWN;
    int tx = threadIdx.x & 31, ty = threadIdx.x >> 5;
#pragma unroll
    for (int s2 = 0; s2 < 4; s2++) {
        int cc = c0 + ty + 8 * s2;
        tile[ty + 8 * s2][tx] = In[(size_t)cc * HWN + r0 + tx];
    }
    __syncthreads();
    size_t base = (size_t)b * CHWN;
#pragma unroll
    for (int s2 = 0; s2 < 4; s2++) {
        int r = r0 + ty + 8 * s2;
        size_t idx = base + (size_t)r * CN + c0 + tx;
        out[idx] = tile[tx][ty + 8 * s2] + Fi[idx] + Fw[idx];
    }
}

// ---------------- launch ----------------
extern "C" void kernel_launch(void* const* d_in, const int* in_sizes, int n_in,
                              void* d_out, int out_size) {
    const float* Fi = (const float*)d_in[0];
    const float* Fw = (const float*)d_in[1];
    const float* g1 = (const float*)d_in[2];
    const float* g2 = (const float*)d_in[3];

    const float *qw1, *kw1, *vw1, *qw2, *kw2, *vw2;
    const float *qb1, *kb1, *vb1, *qb2, *kb2, *vb2;
    const float *qdw1, *kdw1, *vdw1, *qdw2, *kdw2, *vdw2;
    const float *qdb1, *kdb1, *vdb1, *qdb2, *kdb2, *vdb2;
    const float *lw, *lb;

    if (in_sizes[5] == CN) {
        qw1 = (const float*)d_in[4];  qb1 = (const float*)d_in[5];
        kw1 = (const float*)d_in[6];  kb1 = (const float*)d_in[7];
        vw1 = (const float*)d_in[8];  vb1 = (const float*)d_in[9];
        qw2 = (const float*)d_in[10]; qb2 = (const float*)d_in[11];
        kw2 = (const float*)d_in[12]; kb2 = (const float*)d_in[13];
        vw2 = (const float*)d_in[14]; vb2 = (const float*)d_in[15];
        qdw1 = (const float*)d_in[16]; qdb1 = (const float*)d_in[17];
        kdw1 = (const float*)d_in[18]; kdb1 = (const float*)d_in[19];
        vdw1 = (const float*)d_in[20]; vdb1 = (const float*)d_in[21];
        qdw2 = (const float*)d_in[22]; qdb2 = (const float*)d_in[23];
        kdw2 = (const float*)d_in[24]; kdb2 = (const float*)d_in[25];
        vdw2 = (const float*)d_in[26]; vdb2 = (const float*)d_in[27];
    } else {
        qw1 = (const float*)d_in[4];  kw1 = (const float*)d_in[5];
        vw1 = (const float*)d_in[6];  qw2 = (const float*)d_in[7];
        kw2 = (const float*)d_in[8];  vw2 = (const float*)d_in[9];
        qb1 = (const float*)d_in[10]; kb1 = (const float*)d_in[11];
        vb1 = (const float*)d_in[12]; qb2 = (const float*)d_in[13];
        kb2 = (const float*)d_in[14]; vb2 = (const float*)d_in[15];
        qdw1 = (const float*)d_in[16]; kdw1 = (const float*)d_in[17];
        vdw1 = (const float*)d_in[18]; qdw2 = (const float*)d_in[19];
        kdw2 = (const float*)d_in[20]; vdw2 = (const float*)d_in[21];
        qdb1 = (const float*)d_in[22]; kdb1 = (const float*)d_in[23];
        vdb1 = (const float*)d_in[24]; qdb2 = (const float*)d_in[25];
        kdb2 = (const float*)d_in[26]; vdb2 = (const float*)d_in[27];
    }
    lw = (const float*)d_in[28];
    lb = (const float*)d_in[29];
    float* out = (float*)d_out;

    cudaFuncSetAttribute(k_ln_c11, cudaFuncAttributeMaxDynamicSharedMemorySize, SMEM_LN);
    cudaFuncSetAttribute(k_qk,     cudaFuncAttributeMaxDynamicSharedMemorySize, SMEM_BF);
    cudaFuncSetAttribute(k_av,     cudaFuncAttributeMaxDynamicSharedMemorySize, SMEM_BF);
    cudaFuncSetAttribute(k_final,  cudaFuncAttributeMaxDynamicSharedMemorySize, SMEM_BF);

    k_splitw <<<dim3(512), 256>>>(qw1, kw1, vw1, qw2, kw2, vw2, lw);
    k_ln_c11 <<<dim3(NPIX / 128, 2), 512, SMEM_LN>>>(Fi, Fw, g1, g2,
                                                     qb1, kb1, vb1, qb2, kb2, vb2);
    k_dw     <<<dim3(2048, BB, 6), 256>>>(qdw1, kdw1, vdw1, qdw2, kdw2, vdw2,
                                          qdb1, kdb1, vdb1, qdb2, kdb2, vdb2);
    k_qk     <<<dim3(NSPLIT, BB, 2), 256, SMEM_BF>>>();
    k_softmax<<<dim3(256), 256>>>();
    k_av     <<<dim3(HWN / 128, BB, 2), 256, SMEM_BF>>>();
    k_final  <<<dim3(HWN / 128, BB), 256, SMEM_BF>>>(lb);
    k_tail   <<<dim3(HWN / 32, CN / 32, BB), 256>>>(Fi, Fw, out);
}

// round 16
// speedup vs baseline: 2.8065x; 1.1783x over previous
#include <cuda_runtime.h>
#include <cuda_bf16.h>
#include <cstdint>

// ---------------- problem constants ----------------
#define BB    8
#define CN    128
#define HN    128
#define WN    128
#define HWN   16384
#define CHWN  (CN*HWN)                 // 2,097,152
#define BCHWN (BB*CHWN)                // 16,777,216
#define NPIX  (BB*HWN)                 // 131,072
#define NSPLIT 16

// bf16 pair layout: [k2][m] of uint2 {hi_bf16x2, lo_bf16x2}, pitch 131
#define PB 131
#define BF_TILE (32*PB*8)              // 33568
#define SMEM_BF (2*BF_TILE + 512)
// ln smem: B2a | B2b | union{Xraw[128][129], A2} | stats
#define LN_XRAW   (2*BF_TILE)
#define LN_STATS  (2*BF_TILE + 66048)
#define SMEM_LN2  (LN_STATS + 5632)    // 138,784 B

// ---------------- device scratch ----------------
__device__ float g_pre [6ull*BCHWN];                        // conv1x1 out (fp32)
__device__ __align__(16) uint32_t g_postall[6ull*BCHWN];    // dw out, bf16 packed
__device__ float g_Spart[2ull*NSPLIT*BB*CN*CN];
__device__ __align__(16) uint32_t g_S2[2ull*BB*CN*CN];      // softmax (bf16 packed)
__device__ __align__(16) uint32_t g_A [2ull*BCHWN];         // attn out (bf16 packed)
__device__ float g_lin [1ull*BCHWN];
__device__ __align__(16) uint32_t g_w2b [6*CN*CN];          // 1x1 W (bf16 packed)
__device__ __align__(16) uint32_t g_lw2b[2*CN*CN];          // lw (bf16 packed)

// ---------------- splits ----------------
__device__ __forceinline__ uint32_t bsplit(float x) {       // bf16 hi/lo packed
    __nv_bfloat16 h = __float2bfloat16(x);
    float l = x - __bfloat162float(h);
    __nv_bfloat16 lo = __float2bfloat16(l);
    return ((uint32_t)__bfloat16_as_ushort(lo) << 16) |
           (uint32_t)__bfloat16_as_ushort(h);
}
// pack two values' hi parts and lo parts into uint2 {hi_bf16x2, lo_bf16x2}
__device__ __forceinline__ uint2 bpack2(float v0, float v1) {
    __nv_bfloat16 h0 = __float2bfloat16(v0);
    __nv_bfloat16 h1 = __float2bfloat16(v1);
    __nv_bfloat16 l0 = __float2bfloat16(v0 - __bfloat162float(h0));
    __nv_bfloat16 l1 = __float2bfloat16(v1 - __bfloat162float(h1));
    uint2 r;
    r.x = ((uint32_t)__bfloat16_as_ushort(h1) << 16) | (uint32_t)__bfloat16_as_ushort(h0);
    r.y = ((uint32_t)__bfloat16_as_ushort(l1) << 16) | (uint32_t)__bfloat16_as_ushort(l0);
    return r;
}

// ---------------- mma wrapper ----------------
__device__ __forceinline__ void mmabf(float c[4], const uint32_t a[4],
                                      uint32_t b0, uint32_t b1) {
    asm volatile(
        "mma.sync.aligned.m16n8k16.row.col.f32.bf16.bf16.f32 "
        "{%0,%1,%2,%3},{%4,%5,%6,%7},{%8,%9},{%0,%1,%2,%3};"
        : "+f"(c[0]), "+f"(c[1]), "+f"(c[2]), "+f"(c[3])
        : "r"(a[0]), "r"(a[1]), "r"(a[2]), "r"(a[3]), "r"(b0), "r"(b1));
}
#define ZERO_C48(c4) {                                 \
    _Pragma("unroll") for (int mi = 0; mi < 2; mi++)   \
    _Pragma("unroll") for (int ni = 0; ni < 8; ni++)   \
    _Pragma("unroll") for (int t = 0; t < 4; t++) (c4)[mi][ni][t] = 0.f; }

// bf16 pair KM/KM, K=64 chunk (32 k2-rows), warp tile 32x64
__device__ __forceinline__ void gemm_bf(const uint2* __restrict__ A2,
                                        const uint2* __restrict__ B2,
                                        float c4[2][8][4],
                                        int m0, int n0w, int r, int q) {
#pragma unroll
    for (int ks = 0; ks < 4; ks++) {
        int k2a = ks * 8 + q, k2b = ks * 8 + q + 4;
        uint32_t ah[2][4], al[2][4];
#pragma unroll
        for (int mi = 0; mi < 2; mi++) {
            int m = m0 + mi * 16 + r;
            uint2 u0 = A2[k2a * PB + m];
            uint2 u1 = A2[k2a * PB + m + 8];
            uint2 u2 = A2[k2b * PB + m];
            uint2 u3 = A2[k2b * PB + m + 8];
            ah[mi][0] = u0.x; ah[mi][1] = u1.x; ah[mi][2] = u2.x; ah[mi][3] = u3.x;
            al[mi][0] = u0.y; al[mi][1] = u1.y; al[mi][2] = u2.y; al[mi][3] = u3.y;
        }
#pragma unroll
        for (int ni = 0; ni < 8; ni++) {
            int col = n0w + ni * 8 + r;
            uint2 v0 = B2[k2a * PB + col];
            uint2 v1 = B2[k2b * PB + col];
#pragma unroll
            for (int mi = 0; mi < 2; mi++) {
                mmabf(c4[mi][ni], ah[mi], v0.x, v1.x);
                mmabf(c4[mi][ni], al[mi], v0.x, v1.x);
                mmabf(c4[mi][ni], ah[mi], v0.y, v1.y);
            }
        }
    }
}

// ---------------- kernel 0b: pre-split weights (all bf16 packed) -----------
__global__ __launch_bounds__(256) void k_splitw(
    const float* w0, const float* w1, const float* w2,
    const float* w3, const float* w4, const float* w5,
    const float* lw) {
    int i = blockIdx.x * 256 + threadIdx.x;
    if (i < 6 * CN * CN) {
        const float* srcs[6] = {w0, w1, w2, w3, w4, w5};
        g_w2b[i] = bsplit(srcs[i >> 14][i & 16383]);
    } else {
        int j = i - 6 * CN * CN;
        g_lw2b[j] = bsplit(lw[j]);
    }
}

// ---------------- kernel 1: fused stats + LN + 3x(1x1 conv) (bf16x3) ------
// C[o][pix] = sum_c W[o][c] * Xn[pix][c]; A=W [c2][o], B=Xn [c2][pix]
__global__ __launch_bounds__(256, 1) void k_ln_c11(
    const float* __restrict__ Fi, const float* __restrict__ Fw,
    const float* __restrict__ g1, const float* __restrict__ g2,
    const float* bq, const float* bk, const float* bv,
    const float* bq2, const float* bk2, const float* bv2) {
    extern __shared__ char smraw[];
    uint2* B2a = (uint2*)smraw;
    uint2* B2b = (uint2*)(smraw + BF_TILE);
    float* Xraw = (float*)(smraw + LN_XRAW);           // [128][129]
    uint2* A2   = (uint2*)(smraw + LN_XRAW);           // union with Xraw
    float* mu_s = (float*)(smraw + LN_STATS);
    float* rs_s = mu_s + 128;
    float* gm_s = rs_s + 128;
    float* redS = gm_s + 128;                          // [2][128]
    float* redQ = redS + 256;                          // [2][128]

    int tid = threadIdx.x, wid = tid >> 5, lane = tid & 31;
    int inp = blockIdx.y;
    int p0 = blockIdx.x * 128;
    int b = p0 >> 14, pix0 = p0 & (HWN - 1);
    const float* X = inp ? Fw : Fi;
    const float* gamma = inp ? g2 : g1;
    const float* Bs3[3] = { inp ? bq2 : bq, inp ? bk2 : bk, inp ? bv2 : bv };

    if (tid < 128) gm_s[tid] = gamma[tid];

    // phase A: raw X tile to smem
    const float* Xb = X + (size_t)b * CHWN + pix0;
#pragma unroll 8
    for (int it = 0; it < 64; it++) {
        int idx = it * 256 + tid;
        Xraw[(idx >> 7) * 129 + (idx & 127)] = Xb[(size_t)(idx >> 7) * HWN + (idx & 127)];
    }
    __syncthreads();

    // phase B: per-pixel LN stats
    {
        int p = tid & 127, g = tid >> 7;               // g in {0,1}, 64 channels each
        float s = 0.f, ss = 0.f;
#pragma unroll 8
        for (int kc = g * 64; kc < g * 64 + 64; kc++) {
            float v = Xraw[kc * 129 + p];
            s += v; ss += v * v;
        }
        redS[g * 128 + p] = s;
        redQ[g * 128 + p] = ss;
    }
    __syncthreads();
    if (tid < 128) {
        float s  = redS[tid] + redS[128 + tid];
        float ss = redQ[tid] + redQ[128 + tid];
        float m = s * (1.f / CN);
        mu_s[tid] = m;
        rs_s[tid] = rsqrtf(ss * (1.f / CN) - m * m + 1e-5f);
    }
    __syncthreads();

    // phase C: normalize + bf16-pair pack into B tiles [c2][pix]
#pragma unroll 8
    for (int it = 0; it < 32; it++) {
        int idx = it * 256 + tid;                      // 8192 = 64 c2 x 128 p
        int c2 = idx >> 7, p = idx & 127;
        float mu = mu_s[p], rs = rs_s[p];
        float v0 = (Xraw[(2 * c2) * 129 + p] - mu) * rs * gm_s[2 * c2];
        float v1 = (Xraw[(2 * c2 + 1) * 129 + p] - mu) * rs * gm_s[2 * c2 + 1];
        uint2 pk = bpack2(v0, v1);
        if (c2 < 32) B2a[c2 * PB + p] = pk;
        else         B2b[(c2 - 32) * PB + p] = pk;
    }
    __syncthreads();                                   // Xraw dead after this

    int m0 = (wid & 3) * 32, n0w = (wid >> 2) * 64;
    int r = lane >> 2, q = lane & 3;

    for (int i = 0; i < 3; i++) {
        const uint32_t* Wsrc = g_w2b + (size_t)(inp * 3 + i) * CN * CN;
        float c4[2][8][4];
        ZERO_C48(c4);
#pragma unroll 2
        for (int ch = 0; ch < 2; ch++) {
            __syncthreads();
#pragma unroll
            for (int it = 0; it < 8; it++) {           // A = W [c2][o]
                int idx = it * 256 + tid;
                int cg = idx & 15, o = idx >> 4;
                uint4 wv = *(const uint4*)(Wsrc + o * CN + ch * 64 + 4 * cg);
                A2[(2 * cg) * PB + o] =
                    make_uint2(__byte_perm(wv.x, wv.y, 0x5410), __byte_perm(wv.x, wv.y, 0x7632));
                A2[(2 * cg + 1) * PB + o] =
                    make_uint2(__byte_perm(wv.z, wv.w, 0x5410), __byte_perm(wv.z, wv.w, 0x7632));
            }
            __syncthreads();
            gemm_bf(A2, ch ? B2b : B2a, c4, m0, n0w, r, q);
        }
        const float* bias = Bs3[i];
        float* Ob = g_pre + ((size_t)(inp * 3 + i) * BB + b) * CHWN;
#pragma unroll
        for (int mi = 0; mi < 2; mi++) {
            int o0 = m0 + mi * 16 + r;
            float bo0 = __ldg(&bias[o0]), bo1 = __ldg(&bias[o0 + 8]);
#pragma unroll
            for (int ni = 0; ni < 8; ni++) {
                int col = pix0 + n0w + ni * 8 + 2 * q;
                *(float2*)&Ob[(size_t)o0 * HWN + col] =
                    make_float2(c4[mi][ni][0] + bo0, c4[mi][ni][1] + bo0);
                *(float2*)&Ob[(size_t)(o0 + 8) * HWN + col] =
                    make_float2(c4[mi][ni][2] + bo1, c4[mi][ni][3] + bo1);
            }
        }
    }
}

// ---------------- kernel 2: depthwise 3x3, smem-tiled, bf16 out ------------
__global__ __launch_bounds__(256) void k_dw(
    const float* d0, const float* d1, const float* d2,
    const float* d3, const float* d4, const float* d5,
    const float* e0, const float* e1, const float* e2,
    const float* e3, const float* e4, const float* e5) {
    __shared__ float s[10][128];
    int br = blockIdx.z, b = blockIdx.y;
    int c = blockIdx.x >> 4, rg = blockIdx.x & 15;
    int h0 = rg * 8;
    int tid = threadIdx.x;
    const float* Wd6[6] = {d0, d1, d2, d3, d4, d5};
    const float* Bd6[6] = {e0, e1, e2, e3, e4, e5};
    const float* In = g_pre + ((size_t)br * BB + b) * CHWN + (size_t)c * HWN;

#pragma unroll
    for (int i = tid; i < 1280; i += 256) {
        int row = i >> 7, col = i & 127;
        int gh = h0 - 1 + row;
        s[row][col] = ((unsigned)gh < 128u) ? In[(size_t)gh * WN + col] : 0.f;
    }
    __syncthreads();

    const float* Wd = Wd6[br] + c * 9;
    float kw[9];
#pragma unroll
    for (int i = 0; i < 9; i++) kw[i] = __ldg(&Wd[i]);
    float bias = __ldg(&Bd6[br][c]);

    int t4 = tid * 4, lr = t4 >> 7, w0 = t4 & 127;
    float a0 = bias, a1 = bias, a2 = bias, a3 = bias;
#pragma unroll
    for (int dy = 0; dy < 3; dy++) {
        const float* row = s[lr + dy];
        float4 v = *(const float4*)(row + w0);
        float xl = (w0 > 0)   ? row[w0 - 1] : 0.f;
        float xr = (w0 < 124) ? row[w0 + 4] : 0.f;
        float k0 = kw[dy * 3], k1 = kw[dy * 3 + 1], k2 = kw[dy * 3 + 2];
        a0 += k0 * xl  + k1 * v.x + k2 * v.y;
        a1 += k0 * v.x + k1 * v.y + k2 * v.z;
        a2 += k0 * v.y + k1 * v.z + k2 * v.w;
        a3 += k0 * v.z + k1 * v.w + k2 * xr;
    }
    uint32_t* Op = g_postall + ((size_t)br * BB + b) * CHWN + (size_t)c * HWN
                 + (size_t)h0 * WN + t4;
    *(uint4*)Op = make_uint4(bsplit(a0), bsplit(a1), bsplit(a2), bsplit(a3));
}

// ---------------- kernel 3: S partials (bf16x3) ----------------
// C[c][d] = sum_n Q[n][c] K[n][d]
__global__ __launch_bounds__(256, 2) void k_qk() {
    extern __shared__ char smraw[];
    uint2* A2 = (uint2*)smraw;
    uint2* B2 = (uint2*)(smraw + BF_TILE);
    int tid = threadIdx.x, wid = tid >> 5, lane = tid & 31;
    int s = blockIdx.x, b = blockIdx.y, att = blockIdx.z;
    int qbr = (att == 0) ? 0 : 3;
    int kbr = (att == 0) ? 4 : 1;
    const uint32_t* Qp = g_postall + ((size_t)qbr * BB + b) * CHWN;
    const uint32_t* Kp = g_postall + ((size_t)kbr * BB + b) * CHWN;

    int m0 = (wid & 3) * 32, n0w = (wid >> 2) * 64;
    int r = lane >> 2, q = lane & 3;
    float c4[2][8][4];
    ZERO_C48(c4);

    for (int ch = 0; ch < 16; ch++) {
        size_t nb = ((size_t)s * 1024 + ch * 64) * CN;
        __syncthreads();
#pragma unroll
        for (int it = 0; it < 4; it++) {
            int idx = it * 256 + tid;
            int n2 = idx >> 5, c4i = (idx & 31) * 4;
            uint4 q0 = *(const uint4*)(Qp + nb + (size_t)(2 * n2) * CN + c4i);
            uint4 q1 = *(const uint4*)(Qp + nb + (size_t)(2 * n2 + 1) * CN + c4i);
            uint2* da = A2 + n2 * PB + c4i;
            da[0] = make_uint2(__byte_perm(q0.x, q1.x, 0x5410), __byte_perm(q0.x, q1.x, 0x7632));
            da[1] = make_uint2(__byte_perm(q0.y, q1.y, 0x5410), __byte_perm(q0.y, q1.y, 0x7632));
            da[2] = make_uint2(__byte_perm(q0.z, q1.z, 0x5410), __byte_perm(q0.z, q1.z, 0x7632));
            da[3] = make_uint2(__byte_perm(q0.w, q1.w, 0x5410), __byte_perm(q0.w, q1.w, 0x7632));
            uint4 k0 = *(const uint4*)(Kp + nb + (size_t)(2 * n2) * CN + c4i);
            uint4 k1 = *(const uint4*)(Kp + nb + (size_t)(2 * n2 + 1) * CN + c4i);
            uint2* db = B2 + n2 * PB + c4i;
            db[0] = make_uint2(__byte_perm(k0.x, k1.x, 0x5410), __byte_perm(k0.x, k1.x, 0x7632));
            db[1] = make_uint2(__byte_perm(k0.y, k1.y, 0x5410), __byte_perm(k0.y, k1.y, 0x7632));
            db[2] = make_uint2(__byte_perm(k0.z, k1.z, 0x5410), __byte_perm(k0.z, k1.z, 0x7632));
            db[3] = make_uint2(__byte_perm(k0.w, k1.w, 0x5410), __byte_perm(k0.w, k1.w, 0x7632));
        }
        __syncthreads();
        gemm_bf(A2, B2, c4, m0, n0w, r, q);
    }

    float* Sp = g_Spart + ((size_t)(att * NSPLIT + s) * BB + b) * (CN * CN);
#pragma unroll
    for (int mi = 0; mi < 2; mi++) {
        int c0 = m0 + mi * 16 + r;
#pragma unroll
        for (int ni = 0; ni < 8; ni++) {
            int col = n0w + ni * 8 + 2 * q;
            *(float2*)&Sp[c0 * CN + col] = make_float2(c4[mi][ni][0], c4[mi][ni][1]);
            *(float2*)&Sp[(c0 + 8) * CN + col] = make_float2(c4[mi][ni][2], c4[mi][ni][3]);
        }
    }
}

// ---------------- kernel 4: reduce partials + softmax -> bf16 packed --------
__global__ __launch_bounds__(256) void k_softmax() {
    int row  = blockIdx.x * 8 + (threadIdx.x >> 5);
    int lane = threadIdx.x & 31;
    int att = row >> 10, rb = row & 1023, b = rb >> 7, c = rb & 127;
    float v[4];
#pragma unroll
    for (int q = 0; q < 4; q++) {
        int d = lane + 32 * q;
        float s = 0.f;
        for (int sp = 0; sp < NSPLIT; sp++)
            s += g_Spart[((size_t)(att * NSPLIT + sp) * BB + b) * (CN * CN) + c * CN + d];
        v[q] = s;
    }
    float mx = fmaxf(fmaxf(v[0], v[1]), fmaxf(v[2], v[3]));
#pragma unroll
    for (int o = 16; o > 0; o >>= 1) mx = fmaxf(mx, __shfl_xor_sync(0xffffffffu, mx, o));
    float e[4], sum = 0.f;
#pragma unroll
    for (int q = 0; q < 4; q++) { e[q] = __expf(v[q] - mx); sum += e[q]; }
#pragma unroll
    for (int o = 16; o > 0; o >>= 1) sum += __shfl_xor_sync(0xffffffffu, sum, o);
    float inv = 1.f / sum;
#pragma unroll
    for (int q = 0; q < 4; q++)
        g_S2[(size_t)(att * BB + b) * (CN * CN) + c * CN + lane + 32 * q] =
            bsplit(e[q] * inv);
}

// ---------------- kernel 5: A@V (bf16x3) ----------------
__global__ __launch_bounds__(256, 2) void k_av() {
    extern __shared__ char smraw[];
    uint2* A2 = (uint2*)smraw;
    uint2* B2 = (uint2*)(smraw + BF_TILE);
    int tid = threadIdx.x, wid = tid >> 5, lane = tid & 31;
    int nt = blockIdx.x, b = blockIdx.y, att = blockIdx.z;
    int vbr = (att == 0) ? 5 : 2;
    const uint32_t* Sp = g_S2 + (size_t)(att * BB + b) * (CN * CN);
    const uint32_t* Vp = g_postall + ((size_t)vbr * BB + b) * CHWN;
    int n0 = nt * 128;

    int m0 = (wid & 3) * 32, n0w = (wid >> 2) * 64;
    int r = lane >> 2, q = lane & 3;
    float c4[2][8][4];
    ZERO_C48(c4);

#pragma unroll 2
    for (int chk = 0; chk < 2; chk++) {
        int d0 = chk * 64;
        __syncthreads();
#pragma unroll
        for (int it = 0; it < 4; it++) {               // A = V [d2][p]
            int idx = it * 256 + tid;
            int d2 = idx >> 5, p4 = (idx & 31) * 4;
            uint4 v0 = *(const uint4*)(Vp + (size_t)(d0 + 2 * d2) * HWN + n0 + p4);
            uint4 v1 = *(const uint4*)(Vp + (size_t)(d0 + 2 * d2 + 1) * HWN + n0 + p4);
            uint2* dst = A2 + d2 * PB + p4;
            dst[0] = make_uint2(__byte_perm(v0.x, v1.x, 0x5410), __byte_perm(v0.x, v1.x, 0x7632));
            dst[1] = make_uint2(__byte_perm(v0.y, v1.y, 0x5410), __byte_perm(v0.y, v1.y, 0x7632));
            dst[2] = make_uint2(__byte_perm(v0.z, v1.z, 0x5410), __byte_perm(v0.z, v1.z, 0x7632));
            dst[3] = make_uint2(__byte_perm(v0.w, v1.w, 0x5410), __byte_perm(v0.w, v1.w, 0x7632));
        }
#pragma unroll
        for (int it = 0; it < 8; it++) {               // B = S [d2][c]
            int idx = it * 256 + tid;
            int d2g = idx & 15, c = idx >> 4;
            uint4 sv = *(const uint4*)(Sp + c * CN + d0 + 4 * d2g);
            B2[(2 * d2g) * PB + c] =
                make_uint2(__byte_perm(sv.x, sv.y, 0x5410), __byte_perm(sv.x, sv.y, 0x7632));
            B2[(2 * d2g + 1) * PB + c] =
                make_uint2(__byte_perm(sv.z, sv.w, 0x5410), __byte_perm(sv.z, sv.w, 0x7632));
        }
        __syncthreads();
        gemm_bf(A2, B2, c4, m0, n0w, r, q);
    }

    uint32_t* Out = g_A + (size_t)att * BCHWN + (size_t)b * CHWN;
#pragma unroll
    for (int mi = 0; mi < 2; mi++) {
        int rr = m0 + mi * 16 + r;
#pragma unroll
        for (int ni = 0; ni < 8; ni++) {
            int cc = n0w + ni * 8 + 2 * q;
            Out[(size_t)cc * HWN + n0 + rr]           = bsplit(c4[mi][ni][0]);
            Out[(size_t)(cc + 1) * HWN + n0 + rr]     = bsplit(c4[mi][ni][1]);
            Out[(size_t)cc * HWN + n0 + rr + 8]       = bsplit(c4[mi][ni][2]);
            Out[(size_t)(cc + 1) * HWN + n0 + rr + 8] = bsplit(c4[mi][ni][3]);
        }
    }
}

// ---------------- kernel 6: final linear (bf16x3) ----------------
__global__ __launch_bounds__(256, 2) void k_final(const float* __restrict__ lb) {
    extern __shared__ char smraw[];
    uint2* A2 = (uint2*)smraw;
    uint2* B2 = (uint2*)(smraw + BF_TILE);
    int tid = threadIdx.x, wid = tid >> 5, lane = tid & 31;
    int nt = blockIdx.x, b = blockIdx.y;
    int n0 = nt * 128;

    int m0 = (wid & 3) * 32, n0w = (wid >> 2) * 64;
    int r = lane >> 2, q = lane & 3;
    float c4[2][8][4];
    ZERO_C48(c4);

    for (int chk = 0; chk < 4; chk++) {
        int part = chk >> 1, tloc = (chk & 1) * 64;
        const uint32_t* Ap = g_A + ((size_t)part * BB + b) * CHWN + (size_t)n0 * CN;
        __syncthreads();
#pragma unroll
        for (int it = 0; it < 8; it++) {               // A = flat [t2][pix]
            int idx = it * 256 + tid;
            int tg = idx & 15, p = idx >> 4;
            uint4 av = *(const uint4*)(Ap + p * CN + tloc + 4 * tg);
            A2[(2 * tg) * PB + p] =
                make_uint2(__byte_perm(av.x, av.y, 0x5410), __byte_perm(av.x, av.y, 0x7632));
            A2[(2 * tg + 1) * PB + p] =
                make_uint2(__byte_perm(av.z, av.w, 0x5410), __byte_perm(av.z, av.w, 0x7632));
        }
#pragma unroll
        for (int it = 0; it < 8; it++) {               // B = lw [t2][co]
            int idx = it * 256 + tid;
            int tg = idx & 15, co = idx >> 4;
            uint4 lv = *(const uint4*)(g_lw2b + co * 256 + part * 128 + tloc + 4 * tg);
            B2[(2 * tg) * PB + co] =
                make_uint2(__byte_perm(lv.x, lv.y, 0x5410), __byte_perm(lv.x, lv.y, 0x7632));
            B2[(2 * tg + 1) * PB + co] =
                make_uint2(__byte_perm(lv.z, lv.w, 0x5410), __byte_perm(lv.z, lv.w, 0x7632));
        }
        __syncthreads();
        gemm_bf(A2, B2, c4, m0, n0w, r, q);
    }

    float* Ob = g_lin + (size_t)b * CHWN;
#pragma unroll
    for (int mi = 0; mi < 2; mi++) {
        int p0r = n0 + m0 + mi * 16 + r;
#pragma unroll
        for (int ni = 0; ni < 8; ni++) {
            int col = n0w + ni * 8 + 2 * q;
            float b0 = __ldg(&lb[col]), b1 = __ldg(&lb[col + 1]);
            *(float2*)&Ob[(size_t)p0r * CN + col] =
                make_float2(c4[mi][ni][0] + b0, c4[mi][ni][1] + b1);
            *(float2*)&Ob[(size_t)(p0r + 8) * CN + col] =
                make_float2(c4[mi][ni][2] + b0, c4[mi][ni][3] + b1);
        }
    }
}

// ---------------- kernel 7: tail transpose + residual ----------------
__global__ __launch_bounds__(256) void k_tail(const float* __restrict__ Fi,
                                              const float* __restrict__ Fw,
                                              float* __restrict__ out) {
    __shared__ float tile[32][33];
    int b  = blockIdx.z;
    int r0 = blockIdx.x * 32;
    int c0 = blockIdx.y * 32;
    const float* In = g_lin + (size_t)b * CHWN;
    int tx = threadIdx.x & 31, ty = threadIdx.x >> 5;
#pragma unroll
    for (int s2 = 0; s2 < 4; s2++) {
        int cc = c0 + ty + 8 * s2;
        tile[ty + 8 * s2][tx] = In[(size_t)cc * HWN + r0 + tx];
    }
    __syncthreads();
    size_t base = (size_t)b * CHWN;
#pragma unroll
    for (int s2 = 0; s2 < 4; s2++) {
        int r = r0 + ty + 8 * s2;
        size_t idx = base + (size_t)r * CN + c0 + tx;
        out[idx] = tile[tx][ty + 8 * s2] + Fi[idx] + Fw[idx];
    }
}

// ---------------- launch ----------------
extern "C" void kernel_launch(void* const* d_in, const int* in_sizes, int n_in,
                              void* d_out, int out_size) {
    const float* Fi = (const float*)d_in[0];
    const float* Fw = (const float*)d_in[1];
    const float* g1 = (const float*)d_in[2];
    const float* g2 = (const float*)d_in[3];

    const float *qw1, *kw1, *vw1, *qw2, *kw2, *vw2;
    const float *qb1, *kb1, *vb1, *qb2, *kb2, *vb2;
    const float *qdw1, *kdw1, *vdw1, *qdw2, *kdw2, *vdw2;
    const float *qdb1, *kdb1, *vdb1, *qdb2, *kdb2, *vdb2;
    const float *lw, *lb;

    if (in_sizes[5] == CN) {
        qw1 = (const float*)d_in[4];  qb1 = (const float*)d_in[5];
        kw1 = (const float*)d_in[6];  kb1 = (const float*)d_in[7];
        vw1 = (const float*)d_in[8];  vb1 = (const float*)d_in[9];
        qw2 = (const float*)d_in[10]; qb2 = (const float*)d_in[11];
        kw2 = (const float*)d_in[12]; kb2 = (const float*)d_in[13];
        vw2 = (const float*)d_in[14]; vb2 = (const float*)d_in[15];
        qdw1 = (const float*)d_in[16]; qdb1 = (const float*)d_in[17];
        kdw1 = (const float*)d_in[18]; kdb1 = (const float*)d_in[19];
        vdw1 = (const float*)d_in[20]; vdb1 = (const float*)d_in[21];
        qdw2 = (const float*)d_in[22]; qdb2 = (const float*)d_in[23];
        kdw2 = (const float*)d_in[24]; kdb2 = (const float*)d_in[25];
        vdw2 = (const float*)d_in[26]; vdb2 = (const float*)d_in[27];
    } else {
        qw1 = (const float*)d_in[4];  kw1 = (const float*)d_in[5];
        vw1 = (const float*)d_in[6];  qw2 = (const float*)d_in[7];
        kw2 = (const float*)d_in[8];  vw2 = (const float*)d_in[9];
        qb1 = (const float*)d_in[10]; kb1 = (const float*)d_in[11];
        vb1 = (const float*)d_in[12]; qb2 = (const float*)d_in[13];
        kb2 = (const float*)d_in[14]; vb2 = (const float*)d_in[15];
        qdw1 = (const float*)d_in[16]; kdw1 = (const float*)d_in[17];
        vdw1 = (const float*)d_in[18]; qdw2 = (const float*)d_in[19];
        kdw2 = (const float*)d_in[20]; vdw2 = (const float*)d_in[21];
        qdb1 = (const float*)d_in[22]; kdb1 = (const float*)d_in[23];
        vdb1 = (const float*)d_in[24]; qdb2 = (const float*)d_in[25];
        kdb2 = (const float*)d_in[26]; vdb2 = (const float*)d_in[27];
    }
    lw = (const float*)d_in[28];
    lb = (const float*)d_in[29];
    float* out = (float*)d_out;

    cudaFuncSetAttribute(k_ln_c11, cudaFuncAttributeMaxDynamicSharedMemorySize, SMEM_LN2);
    cudaFuncSetAttribute(k_qk,     cudaFuncAttributeMaxDynamicSharedMemorySize, SMEM_BF);
    cudaFuncSetAttribute(k_av,     cudaFuncAttributeMaxDynamicSharedMemorySize, SMEM_BF);
    cudaFuncSetAttribute(k_final,  cudaFuncAttributeMaxDynamicSharedMemorySize, SMEM_BF);

    k_splitw <<<dim3(512), 256>>>(qw1, kw1, vw1, qw2, kw2, vw2, lw);
    k_ln_c11 <<<dim3(NPIX / 128, 2), 256, SMEM_LN2>>>(Fi, Fw, g1, g2,
                                                      qb1, kb1, vb1, qb2, kb2, vb2);
    k_dw     <<<dim3(2048, BB, 6), 256>>>(qdw1, kdw1, vdw1, qdw2, kdw2, vdw2,
                                          qdb1, kdb1, vdb1, qdb2, kdb2, vdb2);
    k_qk     <<<dim3(NSPLIT, BB, 2), 256, SMEM_BF>>>();
    k_softmax<<<dim3(256), 256>>>();
    k_av     <<<dim3(HWN / 128, BB, 2), 256, SMEM_BF>>>();
    k_final  <<<dim3(HWN / 128, BB), 256, SMEM_BF>>>(lb);
    k_tail   <<<dim3(HWN / 32, CN / 32, BB), 256>>>(Fi, Fw, out);
}